// round 12
// baseline (speedup 1.0000x reference)
#include <cuda_runtime.h>
#include <cuda_bf16.h>
#include <cuda_fp16.h>
#include <cstdint>
#include <math.h>

#define BB 8
#define CC 256
#define HH 128
#define WW 128
#define JJ 19
#define SS 512
#define NHH 128
#define NN2 512
#define HW (HH*WW)
#define BJ (BB*JJ)

// ======================= helpers =======================
__device__ __forceinline__ uint32_t smem_u32(const void* p){
  uint32_t a;
  asm("{ .reg .u64 t; cvta.to.shared.u64 t, %1; cvt.u32.u64 %0, t; }" : "=r"(a) : "l"(p));
  return a;
}
__device__ __forceinline__ uint32_t h2_bits(__half2 h){
  return *reinterpret_cast<uint32_t*>(&h);
}
#define LDSM_X4(r0,r1,r2,r3, a) \
  asm volatile("ldmatrix.sync.aligned.m8n8.x4.shared.b16 {%0,%1,%2,%3}, [%4];" \
    : "=r"(r0),"=r"(r1),"=r"(r2),"=r"(r3) : "r"(a))
#define MMA16816(d, a, b) \
  asm volatile("mma.sync.aligned.m16n8k16.row.col.f32.bf16.bf16.f32 " \
    "{%0,%1,%2,%3}, {%4,%5,%6,%7}, {%8,%9}, {%0,%1,%2,%3};" \
    : "+f"((d)[0]),"+f"((d)[1]),"+f"((d)[2]),"+f"((d)[3]) \
    : "r"((a)[0]),"r"((a)[1]),"r"((a)[2]),"r"((a)[3]), "r"((b)[0]),"r"((b)[1]))
#define CP_ASYNC16(dst, src) \
  asm volatile("cp.async.cg.shared.global [%0], [%1], 16;" :: "r"(dst), "l"(src) : "memory")
#define CP_ASYNC16_Z(dst, src, sz) \
  asm volatile("cp.async.cg.shared.global [%0], [%1], 16, %2;" :: "r"(dst), "l"(src), "r"(sz) : "memory")
#define CP_COMMIT() asm volatile("cp.async.commit_group;" ::: "memory")
#define CP_WAIT0()  asm volatile("cp.async.wait_group 0;" ::: "memory")

// ---------------- device scratch ----------------
__device__ float g_ga, g_ba;
__device__ float g_mu[BJ*SS];
__device__ float g_Wt[2*9*SS*CC];
__device__ __align__(16) __half g_GtabH[(size_t)BJ*9*CC*2]; // [bj][tap][c]{gamma,beta} fp16
__device__ __align__(16) float g_SPWt[9*JJ*NHH];            // [tap][j][nh]
__device__ __nv_bfloat16 g_Wh[18*512*64];                   // [chunk=tap*2+half][n][64]
__device__ __nv_bfloat16 g_actvh[(size_t)BB*HW*NHH];        // [b][h][w][nh]
__device__ float g_noiseT[BB*HW];
__device__ __half g_spoutH[(size_t)BB*NN2*HW];              // [b][n][h][w] fp16
__device__ float g_mean[BB*CC], g_rstd[BB*CC];

// ---------------- stream/event for graph fork-join (created pre-capture) ----------------
static cudaStream_t g_s2 = nullptr;
static cudaEvent_t g_evF = nullptr, g_evJ = nullptr;
namespace {
struct StreamInit {
  StreamInit(){
    if (cudaStreamCreateWithFlags(&g_s2, cudaStreamNonBlocking) != cudaSuccess){ g_s2 = nullptr; return; }
    if (cudaEventCreateWithFlags(&g_evF, cudaEventDisableTiming) != cudaSuccess ||
        cudaEventCreateWithFlags(&g_evJ, cudaEventDisableTiming) != cudaSuccess){
      g_s2 = nullptr;
    }
  }
};
static StreamInit g_stream_init;
}

// ---------------- tiny init ----------------
__global__ void k_init(const float* __restrict__ bg, const float* __restrict__ bb){
  g_ga = 1.f/(1.f+expf(-bg[0]));
  g_ba = 1.f/(1.f+expf(-bb[0]));
}

__global__ void k_noiseT(const float* __restrict__ noise){
  __shared__ float t[32][33];
  int b = blockIdx.z;
  int h0 = blockIdx.x*32, w0 = blockIdx.y*32;
  int w = w0 + threadIdx.y, h = h0 + threadIdx.x;
  t[threadIdx.y][threadIdx.x] = noise[(b*WW + w)*HH + h];
  __syncthreads();
  h = h0 + threadIdx.y; w = w0 + threadIdx.x;
  g_noiseT[(b*HH + h)*WW + w] = t[threadIdx.x][threadIdx.y];
}

__global__ void k_mu(const float* __restrict__ style, const float* __restrict__ fcw,
                     const float* __restrict__ fcb){
  int b = blockIdx.x / JJ, j = blockIdx.x % JJ;
  __shared__ __align__(16) float sv[SS];
  for (int i=threadIdx.x;i<SS;i+=256) sv[i]=style[((size_t)b*JJ+j)*SS+i];
  __syncthreads();
  const float4* s4 = (const float4*)sv;
  #pragma unroll
  for (int oo=0;oo<2;oo++){
    int o = threadIdx.x + oo*256;
    const float4* w4 = (const float4*)(fcw + ((size_t)j*SS + o)*SS);
    float a = 0.f;
    for(int i=0;i<SS/4;i++){
      float4 wv=w4[i], svv=s4[i];
      a = fmaf(wv.x,svv.x,a); a = fmaf(wv.y,svv.y,a);
      a = fmaf(wv.z,svv.z,a); a = fmaf(wv.w,svv.w,a);
    }
    g_mu[((size_t)b*JJ+j)*SS+o]=fmaxf(a + fcb[j*SS+o],0.f);
  }
}

__global__ void k_wt(const float* __restrict__ gw, const float* __restrict__ bw){
  int idx = blockIdx.x*256+threadIdx.x;
  int c = idx % CC; int s = (idx/CC)%SS; int tap = (idx/(CC*SS))%9; int t = idx/(CC*SS*9);
  const float* w = t? bw : gw;
  float sc = t? g_ba : g_ga;
  g_Wt[idx] = sc * w[((size_t)c*SS+s)*9+tap];
}

__global__ void k_gtab(){
  int ttap = blockIdx.x;           // t*9+tap
  int mc = blockIdx.y;
  int c = threadIdx.x;
  __shared__ float smu[8][128];
  float acc[8];
  #pragma unroll
  for(int m=0;m<8;m++)acc[m]=0.f;
  for(int kc=0;kc<4;kc++){
    for(int i=threadIdx.x;i<8*128;i+=256){
      int m=i>>7,k=i&127;
      smu[m][k]=g_mu[(size_t)(mc*8+m)*SS + kc*128 + k];
    }
    __syncthreads();
    const float* wp = g_Wt + ((size_t)ttap*SS + kc*128)*CC + c;
    #pragma unroll 4
    for(int k=0;k<128;k++){
      float wv = wp[(size_t)k*CC];
      #pragma unroll
      for(int m=0;m<8;m++) acc[m]=fmaf(wv,smu[m][k],acc[m]);
    }
    __syncthreads();
  }
  int t=ttap/9, tap=ttap%9;
  #pragma unroll
  for(int m=0;m<8;m++){
    int bj=mc*8+m;
    g_GtabH[(((size_t)bj*9 + tap)*CC + c)*2 + t] = __float2half(acc[m]);
  }
}

__global__ void k_spwt(const float* __restrict__ spw){
  int idx = blockIdx.x*256+threadIdx.x;
  if(idx < 9*JJ*NHH){
    int nh = idx % NHH; int j = (idx/NHH)%JJ; int tap = idx/(NHH*JJ);
    g_SPWt[idx] = spw[(nh*JJ + j)*9 + tap];
  }
}

// pack blend-scaled spade conv weights to bf16 chunk layout [tap*2+half][n][64]
__global__ void k_wh(const float* __restrict__ sgw, const float* __restrict__ sbw,
                     const float* __restrict__ bgp, const float* __restrict__ bbp){
  int idx = blockIdx.x*256 + threadIdx.x;   // 18*512*64
  float ga = 1.f/(1.f+expf(-bgp[0]));
  float ba = 1.f/(1.f+expf(-bbp[0]));
  int l = idx & 63;
  int n = (idx >> 6) & 511;
  int chunk = idx >> 15;
  int tap = chunk >> 1, half = chunk & 1;
  int kc = half*64 + l;
  float v;
  if (n < 256) v = (1.f-ga)*sgw[((size_t)n*NHH + kc)*9 + tap];
  else         v = (1.f-ba)*sbw[((size_t)(n-256)*NHH + kc)*9 + tap];
  g_Wh[idx] = __float2bfloat16(v);
}

// actv = relu(table-sum over label neighborhood + bias), vectorized 4-wide over nh
__global__ void k_actv(const int* __restrict__ seg, const float* __restrict__ spb){
  int b = blockIdx.x >> 7, h = blockIdx.x & 127;
  __shared__ int sL[3][130];
  __shared__ float sB[128];
  int tid = threadIdx.x;
  for(int i=tid;i<3*130;i+=256){
    int dy=i/130, cc=i%130;
    int hh=h+dy-1, ww=cc-1;
    sL[dy][cc] = ((unsigned)hh<HH && (unsigned)ww<WW)? seg[(b*HH+hh)*WW+ww] : -1;
  }
  if (tid < 128) sB[tid] = spb[tid];
  __syncthreads();
  int lane = tid & 31, warp = tid >> 5;
  const float4* T = (const float4*)g_SPWt;
  float b0 = sB[lane*4], b1 = sB[lane*4+1], b2 = sB[lane*4+2], b3 = sB[lane*4+3];
  #pragma unroll 1
  for (int w = warp; w < WW; w += 8){
    float a0=b0, a1=b1, a2=b2, a3=b3;
    #pragma unroll
    for (int dy=0;dy<3;dy++){
      #pragma unroll
      for (int dx=0;dx<3;dx++){
        int L = sL[dy][w+dx];
        if (L >= 0){
          float4 tv = __ldg(T + ((dy*3+dx)*JJ + L)*32 + lane);
          a0+=tv.x; a1+=tv.y; a2+=tv.z; a3+=tv.w;
        }
      }
    }
    __nv_bfloat162 p0 = __floats2bfloat162_rn(fmaxf(a0,0.f), fmaxf(a1,0.f));
    __nv_bfloat162 p1 = __floats2bfloat162_rn(fmaxf(a2,0.f), fmaxf(a3,0.f));
    uint2 pk;
    pk.x = *reinterpret_cast<uint32_t*>(&p0);
    pk.y = *reinterpret_cast<uint32_t*>(&p1);
    *(uint2*)(g_actvh + ((size_t)((b*HH+h)*WW + w))*NHH + lane*4) = pk;
  }
}

__global__ void k_stats(const float* __restrict__ x, const float* __restrict__ nv){
  int bc = blockIdx.x; int b = bc >> 8; int c = bc & 255;
  const float4* xp = (const float4*)(x + (size_t)bc*HW);
  const float4* np = (const float4*)(g_noiseT + (size_t)b*HW);
  float nvc = nv[c];
  float s=0.f, s2=0.f;
  for(int i=threadIdx.x;i<HW/4;i+=256){
    float4 xv = xp[i], nn = np[i];
    float v0 = fmaf(nn.x, nvc, xv.x);
    float v1 = fmaf(nn.y, nvc, xv.y);
    float v2 = fmaf(nn.z, nvc, xv.z);
    float v3 = fmaf(nn.w, nvc, xv.w);
    s += v0+v1+v2+v3;
    s2 = fmaf(v0,v0,s2); s2 = fmaf(v1,v1,s2);
    s2 = fmaf(v2,v2,s2); s2 = fmaf(v3,v3,s2);
  }
  __shared__ float rs[8], rs2[8];
  #pragma unroll
  for(int o=16;o;o>>=1){ s += __shfl_xor_sync(0xffffffffu,s,o); s2 += __shfl_xor_sync(0xffffffffu,s2,o); }
  if((threadIdx.x & 31)==0){ rs[threadIdx.x>>5]=s; rs2[threadIdx.x>>5]=s2; }
  __syncthreads();
  if(threadIdx.x < 32){
    s  = (threadIdx.x<8)? rs[threadIdx.x]  : 0.f;
    s2 = (threadIdx.x<8)? rs2[threadIdx.x] : 0.f;
    #pragma unroll
    for(int o=4;o;o>>=1){ s += __shfl_xor_sync(0xffffffffu,s,o); s2 += __shfl_xor_sync(0xffffffffu,s2,o); }
    if(threadIdx.x==0){
      float m = s * (1.f/HW);
      float var = s2 * (1.f/HW) - m*m;
      g_mean[bc]=m; g_rstd[bc]=rsqrtf(var + 1e-5f);
    }
  }
}

// =================== warp-MMA implicit-GEMM conv3x3 (bf16 HMMA, cp.async) ===================
#define OFF_A0 0
#define OFF_A1 16384
#define OFF_B0 32768
#define OFF_B1 49152
#define OFF_BIAS 67584
#define SMEM_DYN 68096

__device__ __forceinline__ void stage_cp(int c, uint32_t sbase, uint32_t a_off, uint32_t b_off,
                                         int b, int h, int n0, int tid){
  int tap = c >> 1, half = c & 1;
  int dy = tap/3 - 1, dx = tap%3 - 1;
  const float4* srcB = (const float4*)g_Wh + ((size_t)c*512 + n0)*8;
  #pragma unroll
  for (int i = 0; i < 4; i++){
    int idx = tid + i*256;
    int n = idx >> 3, blk = idx & 7;
    uint32_t off = (uint32_t)(n*128 + blk*16);
    off ^= (off>>3)&0x70;
    CP_ASYNC16(sbase + b_off + off, srcB + idx);
  }
  int hh = h + dy;
  #pragma unroll
  for (int i = 0; i < 4; i++){
    int idx = tid + i*256;
    int p = idx >> 3, blk = idx & 7;
    int w = p + dx;
    int ok = ((unsigned)hh < HH) && ((unsigned)w < WW);
    const float4* src = (const float4*)g_actvh +
        ((size_t)((b*HH + (ok?hh:0))*WW + (ok?w:0)))*16 + half*8 + blk;
    uint32_t off = (uint32_t)(p*128 + blk*16);
    off ^= (off>>3)&0x70;
    CP_ASYNC16_Z(sbase + a_off + off, src, ok ? 16 : 0);
  }
  CP_COMMIT();
}

__global__ void __launch_bounds__(256,2) k_mma_conv(const float* __restrict__ sgb,
                                                    const float* __restrict__ sbb,
                                                    const float* __restrict__ bgp,
                                                    const float* __restrict__ bbp){
  extern __shared__ __align__(1024) char sm[];
  uint32_t sbase = smem_u32(sm);
  int tid = threadIdx.x, lane = tid & 31, wid = tid >> 5;
  int n0 = blockIdx.x * 128;
  int h = blockIdx.y, b = blockIdx.z;
  int wm = wid & 3, wn = wid >> 2;

  if (tid < 128){
    int n = n0 + tid;
    float ga = 1.f/(1.f+expf(-bgp[0]));
    float ba = 1.f/(1.f+expf(-bbp[0]));
    float v = (n < 256) ? (1.f-ga)*sgb[n] : (1.f-ba)*sbb[n-256];
    ((float*)(sm + OFF_BIAS))[tid] = v;
  }

  float acc[2][8][4];
  #pragma unroll
  for (int mt=0;mt<2;mt++)
    #pragma unroll
    for (int nt=0;nt<8;nt++)
      #pragma unroll
      for (int q=0;q<4;q++) acc[mt][nt][q]=0.f;

  stage_cp(0, sbase, OFF_A0, OFF_B0, b, h, n0, tid);

  #pragma unroll 1
  for (int c = 0; c < 18; c++){
    CP_WAIT0();
    __syncthreads();
    int buf = c & 1;
    if (c + 1 < 18)
      stage_cp(c+1, sbase, buf ? OFF_A0 : OFF_A1, buf ? OFF_B0 : OFF_B1, b, h, n0, tid);
    uint32_t aB = sbase + (buf ? OFF_A1 : OFF_A0);
    uint32_t bB = sbase + (buf ? OFF_B1 : OFF_B0);
    #pragma unroll
    for (int ks = 0; ks < 4; ks++){
      uint32_t a0[4], a1[4];
      {
        uint32_t row = wm*32 + (lane & 15);
        uint32_t off = row*128 + ks*32 + (lane>>4)*16;
        off ^= (off>>3)&0x70;
        LDSM_X4(a0[0],a0[1],a0[2],a0[3], aB + off);
        row += 16;
        off = row*128 + ks*32 + (lane>>4)*16;
        off ^= (off>>3)&0x70;
        LDSM_X4(a1[0],a1[1],a1[2],a1[3], aB + off);
      }
      uint32_t bf[8][2];
      #pragma unroll
      for (int j = 0; j < 4; j++){
        uint32_t row = wn*64 + j*16 + ((lane>>4)<<3) + (lane & 7);
        uint32_t off = row*128 + ks*32 + ((lane>>3)&1)*16;
        off ^= (off>>3)&0x70;
        uint32_t r0,r1,r2,r3;
        LDSM_X4(r0,r1,r2,r3, bB + off);
        bf[2*j][0]=r0; bf[2*j][1]=r1; bf[2*j+1][0]=r2; bf[2*j+1][1]=r3;
      }
      #pragma unroll
      for (int nt = 0; nt < 8; nt++){
        MMA16816(acc[0][nt], a0, bf[nt]);
        MMA16816(acc[1][nt], a1, bf[nt]);
      }
    }
  }
  __syncthreads();

  // epilogue: restage fp32 to smem [nl][132], then coalesced fp16 stores
  float* sEp = (float*)sm;
  #pragma unroll
  for (int mt=0;mt<2;mt++)
    #pragma unroll
    for (int nt=0;nt<8;nt++){
      int p0 = wm*32 + mt*16 + (lane>>2);
      int nl = wn*64 + nt*8 + (lane&3)*2;
      sEp[nl*132 + p0]       = acc[mt][nt][0];
      sEp[(nl+1)*132 + p0]   = acc[mt][nt][1];
      sEp[nl*132 + p0+8]     = acc[mt][nt][2];
      sEp[(nl+1)*132 + p0+8] = acc[mt][nt][3];
    }
  __syncthreads();
  const float* bias = (const float*)(sm + OFF_BIAS);
  __half* outb = g_spoutH + ((size_t)b*NN2 + n0)*HW + h*WW;
  #pragma unroll 2
  for (int i = tid; i < 128*16; i += 256){
    int nl = i >> 4, q = i & 15;
    float4 v0 = *(float4*)&sEp[nl*132 + q*8];
    float4 v1 = *(float4*)&sEp[nl*132 + q*8 + 4];
    float bv = bias[nl];
    __half2 h0 = __floats2half2_rn(v0.x+bv, v0.y+bv);
    __half2 h1 = __floats2half2_rn(v0.z+bv, v0.w+bv);
    __half2 h2 = __floats2half2_rn(v1.x+bv, v1.y+bv);
    __half2 h3 = __floats2half2_rn(v1.z+bv, v1.w+bv);
    uint4 pk;
    pk.x = h2_bits(h0);
    pk.y = h2_bits(h1);
    pk.z = h2_bits(h2);
    pk.w = h2_bits(h3);
    *(uint4*)&outb[(size_t)nl*HW + q*8] = pk;
  }
}

// ---------------- final: row-block, L1-resident table gather + blend + instance norm ----------------
extern __shared__ float sdyn[];
__global__ void __launch_bounds__(256) k_final(const float* __restrict__ x, const int* __restrict__ seg,
    const float* __restrict__ nv, const float* __restrict__ cgb, const float* __restrict__ cbb,
    float* __restrict__ out){
  int bx = blockIdx.x;           // 0..1023 : (b, h)
  int h = bx & 127, b = bx >> 7;
  __shared__ int sL[3*130];
  float* sg  = sdyn;             // [32 px][257]
  float* sbf = sdyn + 8224;
  float* sM  = sdyn + 16448;
  float* sR  = sdyn + 16704;
  float* sNv = sdyn + 16960;
  int tid = threadIdx.x;
  for(int i=tid;i<3*130;i+=256){
    int dy=i/130, ccc=i%130;
    int hh=h+dy-1, ww2=ccc-1;
    sL[i] = ((unsigned)hh<HH && (unsigned)ww2<WW) ? seg[(b*HH+hh)*WW+ww2] : -1;
  }
  sM[tid]  = g_mean[b*CC+tid];
  sR[tid]  = g_rstd[b*CC+tid];
  sNv[tid] = nv[tid];
  int cq = tid & 63, pg = tid >> 6;
  int c0 = cq*4;
  float bgv[4], bbv[4];
  #pragma unroll
  for(int i=0;i<4;i++){ bgv[i]=g_ga*cgb[c0+i]; bbv[i]=g_ba*cbb[c0+i]; }
  __syncthreads();
  int lane = tid & 31, cw = tid >> 5;
  const char* G = (const char*)g_GtabH;
  #pragma unroll 1
  for (int bt = 0; bt < 4; bt++){
    int w0 = bt*32;
    // phase 1: 4-wide table gather into smem
    #pragma unroll 1
    for (int p = pg*8; p < pg*8+8; p++){
      float ag0=bgv[0], ag1=bgv[1], ag2=bgv[2], ag3=bgv[3];
      float ab0=bbv[0], ab1=bbv[1], ab2=bbv[2], ab3=bbv[3];
      #pragma unroll
      for(int dy=0;dy<3;dy++){
        #pragma unroll
        for(int dx=0;dx<3;dx++){
          int L = sL[dy*130 + w0 + p + dx];
          if(L >= 0){
            float4 raw = __ldg((const float4*)(G + (((size_t)((b*JJ+L)*9 + dy*3+dx))*CC + c0)*4));
            __half2 v0 = *reinterpret_cast<__half2*>(&raw.x);
            __half2 v1 = *reinterpret_cast<__half2*>(&raw.y);
            __half2 v2 = *reinterpret_cast<__half2*>(&raw.z);
            __half2 v3 = *reinterpret_cast<__half2*>(&raw.w);
            float2 f0 = __half22float2(v0), f1 = __half22float2(v1);
            float2 f2 = __half22float2(v2), f3 = __half22float2(v3);
            ag0 += f0.x; ab0 += f0.y;
            ag1 += f1.x; ab1 += f1.y;
            ag2 += f2.x; ab2 += f2.y;
            ag3 += f3.x; ab3 += f3.y;
          }
        }
      }
      sg[p*257+c0]=ag0;   sg[p*257+c0+1]=ag1;
      sg[p*257+c0+2]=ag2; sg[p*257+c0+3]=ag3;
      sbf[p*257+c0]=ab0;   sbf[p*257+c0+1]=ab1;
      sbf[p*257+c0+2]=ab2; sbf[p*257+c0+3]=ab3;
    }
    __syncthreads();
    // phase 2: blend + instance norm, coalesced over pixels
    int ww = w0 + lane;
    float nval = g_noiseT[(b*HH+h)*WW+ww];
    const __half* spg = g_spoutH + (size_t)b*NN2*HW + h*WW + ww;
    #pragma unroll 4
    for(int c = cw; c < CC; c += 8){
      float xv = x[((size_t)(b*CC+c))*HW + h*WW + ww];
      float v = (fmaf(nval, sNv[c], xv) - sM[c])*sR[c];
      float gm = sg[lane*257+c] + __half2float(spg[(size_t)c*HW]);
      float btv = sbf[lane*257+c] + __half2float(spg[(size_t)(c+256)*HW]);
      out[((size_t)(b*CC+c))*HW + h*WW + ww] = fmaf(v, gm, v + btv);
    }
    __syncthreads();
  }
}

// ---------------- launch ----------------
extern "C" void kernel_launch(void* const* d_in, const int* in_sizes, int n_in,
                              void* d_out, int out_size) {
  const float* x     = (const float*)d_in[0];
  const int*   seg   = (const int*)  d_in[1];
  const float* style = (const float*)d_in[2];
  const float* noise = (const float*)d_in[3];
  const float* nv    = (const float*)d_in[4];
  const float* bg    = (const float*)d_in[5];
  const float* bb    = (const float*)d_in[6];
  const float* fcw   = (const float*)d_in[7];
  const float* fcb   = (const float*)d_in[8];
  const float* cgw   = (const float*)d_in[9];
  const float* cgb   = (const float*)d_in[10];
  const float* cbw   = (const float*)d_in[11];
  const float* cbb   = (const float*)d_in[12];
  const float* spw   = (const float*)d_in[13];
  const float* spb   = (const float*)d_in[14];
  const float* sgw   = (const float*)d_in[15];
  const float* sgb   = (const float*)d_in[16];
  const float* sbw   = (const float*)d_in[17];
  const float* sbb   = (const float*)d_in[18];
  float* out = (float*)d_out;

  cudaFuncSetAttribute(k_final, cudaFuncAttributeMaxDynamicSharedMemorySize, 17216*4);
  cudaFuncSetAttribute(k_mma_conv, cudaFuncAttributeMaxDynamicSharedMemorySize, SMEM_DYN);

  bool ov = (g_s2 != nullptr);
  cudaStream_t sb = ov ? g_s2 : (cudaStream_t)0;
  if (ov){
    if (cudaEventRecord(g_evF, 0) != cudaSuccess ||
        cudaStreamWaitEvent(sb, g_evF, 0) != cudaSuccess){
      ov = false; sb = (cudaStream_t)0;
    }
  }

  // chain A (capture stream): actv/wh -> conv  (conv is the 4th launch for ncu)
  k_spwt  <<<(9*JJ*NHH+255)/256,256,0,0>>>(spw);
  k_actv  <<<BB*HH,256,0,0>>>(seg,spb);
  k_wh    <<<(18*512*64)/256,256,0,0>>>(sgw,sbw,bg,bb);
  k_mma_conv<<<dim3(4,HH,BB),256,SMEM_DYN,0>>>(sgb,sbb,bg,bb);

  // chain B (side stream, overlaps the conv): gates, noise, mu, Wt, Gtab, stats
  k_init  <<<1,1,0,sb>>>(bg,bb);
  k_noiseT<<<dim3(4,4,8),dim3(32,32),0,sb>>>(noise);
  k_mu    <<<BJ,256,0,sb>>>(style,fcw,fcb);
  k_wt    <<<(2*9*SS*CC)/256,256,0,sb>>>(cgw,cbw);
  k_gtab  <<<dim3(18,19),256,0,sb>>>();
  k_stats <<<BB*CC,256,0,sb>>>(x,nv);

  if (ov){
    cudaEventRecord(g_evJ, sb);
    cudaStreamWaitEvent(0, g_evJ, 0);
  }
  k_final <<<BB*HH,256,17216*4,0>>>(x,seg,nv,cgb,cbb,out);
}

// round 13
// speedup vs baseline: 1.2884x; 1.2884x over previous
#include <cuda_runtime.h>
#include <cuda_bf16.h>
#include <cuda_fp16.h>
#include <cstdint>
#include <math.h>

#define BB 8
#define CC 256
#define HH 128
#define WW 128
#define JJ 19
#define SS 512
#define NHH 128
#define NN2 512
#define HW (HH*WW)
#define BJ (BB*JJ)

// ======================= helpers =======================
__device__ __forceinline__ uint32_t smem_u32(const void* p){
  uint32_t a;
  asm("{ .reg .u64 t; cvta.to.shared.u64 t, %1; cvt.u32.u64 %0, t; }" : "=r"(a) : "l"(p));
  return a;
}
__device__ __forceinline__ uint32_t h2_bits(__half2 h){
  return *reinterpret_cast<uint32_t*>(&h);
}
#define LDSM_X4(r0,r1,r2,r3, a) \
  asm volatile("ldmatrix.sync.aligned.m8n8.x4.shared.b16 {%0,%1,%2,%3}, [%4];" \
    : "=r"(r0),"=r"(r1),"=r"(r2),"=r"(r3) : "r"(a))
#define MMA16816(d, a, b) \
  asm volatile("mma.sync.aligned.m16n8k16.row.col.f32.bf16.bf16.f32 " \
    "{%0,%1,%2,%3}, {%4,%5,%6,%7}, {%8,%9}, {%0,%1,%2,%3};" \
    : "+f"((d)[0]),"+f"((d)[1]),"+f"((d)[2]),"+f"((d)[3]) \
    : "r"((a)[0]),"r"((a)[1]),"r"((a)[2]),"r"((a)[3]), "r"((b)[0]),"r"((b)[1]))
#define CP_ASYNC16(dst, src) \
  asm volatile("cp.async.cg.shared.global [%0], [%1], 16;" :: "r"(dst), "l"(src) : "memory")
#define CP_ASYNC16_Z(dst, src, sz) \
  asm volatile("cp.async.cg.shared.global [%0], [%1], 16, %2;" :: "r"(dst), "l"(src), "r"(sz) : "memory")
#define CP_COMMIT() asm volatile("cp.async.commit_group;" ::: "memory")
#define CP_WAIT0()  asm volatile("cp.async.wait_group 0;" ::: "memory")

// ---------------- device scratch ----------------
__device__ float g_ga, g_ba;
__device__ float g_mu[BJ*SS];
__device__ float g_Wt[2*9*SS*CC];
__device__ __align__(16) __half g_GtabH[(size_t)BJ*9*CC*2]; // [bj][tap][c]{gamma,beta} fp16
__device__ __align__(16) float g_SPWt[9*JJ*NHH];            // [tap][j][nh]
__device__ __nv_bfloat16 g_Wh[18*512*64];                   // [chunk=tap*2+half][n][64]
__device__ __nv_bfloat16 g_actvh[(size_t)BB*HW*NHH];        // [b][h][w][nh]
__device__ float g_noiseT[BB*HW];
__device__ __half g_spoutH[(size_t)BB*NN2*HW];              // [b][n][h][w] fp16
__device__ float g_mean[BB*CC], g_rstd[BB*CC];

// ---------------- stream/event for graph fork-join (created pre-capture) ----------------
static cudaStream_t g_s2 = nullptr;
static cudaEvent_t g_evF = nullptr, g_evJ = nullptr;
namespace {
struct StreamInit {
  StreamInit(){
    if (cudaStreamCreateWithFlags(&g_s2, cudaStreamNonBlocking) != cudaSuccess){ g_s2 = nullptr; return; }
    if (cudaEventCreateWithFlags(&g_evF, cudaEventDisableTiming) != cudaSuccess ||
        cudaEventCreateWithFlags(&g_evJ, cudaEventDisableTiming) != cudaSuccess){
      g_s2 = nullptr;
    }
  }
};
static StreamInit g_stream_init;
}

// ---------------- tiny init ----------------
__global__ void k_init(const float* __restrict__ bg, const float* __restrict__ bb){
  g_ga = 1.f/(1.f+expf(-bg[0]));
  g_ba = 1.f/(1.f+expf(-bb[0]));
}

__global__ void k_noiseT(const float* __restrict__ noise){
  __shared__ float t[32][33];
  int b = blockIdx.z;
  int h0 = blockIdx.x*32, w0 = blockIdx.y*32;
  int w = w0 + threadIdx.y, h = h0 + threadIdx.x;
  t[threadIdx.y][threadIdx.x] = noise[(b*WW + w)*HH + h];
  __syncthreads();
  h = h0 + threadIdx.y; w = w0 + threadIdx.x;
  g_noiseT[(b*HH + h)*WW + w] = t[threadIdx.x][threadIdx.y];
}

__global__ void k_mu(const float* __restrict__ style, const float* __restrict__ fcw,
                     const float* __restrict__ fcb){
  int b = blockIdx.x / JJ, j = blockIdx.x % JJ;
  __shared__ __align__(16) float sv[SS];
  for (int i=threadIdx.x;i<SS;i+=256) sv[i]=style[((size_t)b*JJ+j)*SS+i];
  __syncthreads();
  const float4* s4 = (const float4*)sv;
  #pragma unroll
  for (int oo=0;oo<2;oo++){
    int o = threadIdx.x + oo*256;
    const float4* w4 = (const float4*)(fcw + ((size_t)j*SS + o)*SS);
    float a = 0.f;
    for(int i=0;i<SS/4;i++){
      float4 wv=w4[i], svv=s4[i];
      a = fmaf(wv.x,svv.x,a); a = fmaf(wv.y,svv.y,a);
      a = fmaf(wv.z,svv.z,a); a = fmaf(wv.w,svv.w,a);
    }
    g_mu[((size_t)b*JJ+j)*SS+o]=fmaxf(a + fcb[j*SS+o],0.f);
  }
}

__global__ void k_wt(const float* __restrict__ gw, const float* __restrict__ bw){
  int idx = blockIdx.x*256+threadIdx.x;
  int c = idx % CC; int s = (idx/CC)%SS; int tap = (idx/(CC*SS))%9; int t = idx/(CC*SS*9);
  const float* w = t? bw : gw;
  float sc = t? g_ba : g_ga;
  g_Wt[idx] = sc * w[((size_t)c*SS+s)*9+tap];
}

__global__ void k_gtab(){
  int ttap = blockIdx.x;           // t*9+tap
  int mc = blockIdx.y;
  int c = threadIdx.x;
  __shared__ float smu[8][128];
  float acc[8];
  #pragma unroll
  for(int m=0;m<8;m++)acc[m]=0.f;
  for(int kc=0;kc<4;kc++){
    for(int i=threadIdx.x;i<8*128;i+=256){
      int m=i>>7,k=i&127;
      smu[m][k]=g_mu[(size_t)(mc*8+m)*SS + kc*128 + k];
    }
    __syncthreads();
    const float* wp = g_Wt + ((size_t)ttap*SS + kc*128)*CC + c;
    #pragma unroll 4
    for(int k=0;k<128;k++){
      float wv = wp[(size_t)k*CC];
      #pragma unroll
      for(int m=0;m<8;m++) acc[m]=fmaf(wv,smu[m][k],acc[m]);
    }
    __syncthreads();
  }
  int t=ttap/9, tap=ttap%9;
  #pragma unroll
  for(int m=0;m<8;m++){
    int bj=mc*8+m;
    g_GtabH[(((size_t)bj*9 + tap)*CC + c)*2 + t] = __float2half(acc[m]);
  }
}

__global__ void k_spwt(const float* __restrict__ spw){
  int idx = blockIdx.x*256+threadIdx.x;
  if(idx < 9*JJ*NHH){
    int nh = idx % NHH; int j = (idx/NHH)%JJ; int tap = idx/(NHH*JJ);
    g_SPWt[idx] = spw[(nh*JJ + j)*9 + tap];
  }
}

// pack blend-scaled spade conv weights to bf16 chunk layout [tap*2+half][n][64]
__global__ void k_wh(const float* __restrict__ sgw, const float* __restrict__ sbw,
                     const float* __restrict__ bgp, const float* __restrict__ bbp){
  int idx = blockIdx.x*256 + threadIdx.x;   // 18*512*64
  float ga = 1.f/(1.f+expf(-bgp[0]));
  float ba = 1.f/(1.f+expf(-bbp[0]));
  int l = idx & 63;
  int n = (idx >> 6) & 511;
  int chunk = idx >> 15;
  int tap = chunk >> 1, half = chunk & 1;
  int kc = half*64 + l;
  float v;
  if (n < 256) v = (1.f-ga)*sgw[((size_t)n*NHH + kc)*9 + tap];
  else         v = (1.f-ba)*sbw[((size_t)(n-256)*NHH + kc)*9 + tap];
  g_Wh[idx] = __float2bfloat16(v);
}

// actv = relu(table-sum over label neighborhood + bias), vectorized 4-wide over nh
__global__ void k_actv(const int* __restrict__ seg, const float* __restrict__ spb){
  int b = blockIdx.x >> 7, h = blockIdx.x & 127;
  __shared__ int sL[3][130];
  __shared__ float sB[128];
  int tid = threadIdx.x;
  for(int i=tid;i<3*130;i+=256){
    int dy=i/130, cc=i%130;
    int hh=h+dy-1, ww=cc-1;
    sL[dy][cc] = ((unsigned)hh<HH && (unsigned)ww<WW)? seg[(b*HH+hh)*WW+ww] : -1;
  }
  if (tid < 128) sB[tid] = spb[tid];
  __syncthreads();
  int lane = tid & 31, warp = tid >> 5;
  const float4* T = (const float4*)g_SPWt;
  float b0 = sB[lane*4], b1 = sB[lane*4+1], b2 = sB[lane*4+2], b3 = sB[lane*4+3];
  #pragma unroll 1
  for (int w = warp; w < WW; w += 8){
    float a0=b0, a1=b1, a2=b2, a3=b3;
    #pragma unroll
    for (int dy=0;dy<3;dy++){
      #pragma unroll
      for (int dx=0;dx<3;dx++){
        int L = sL[dy][w+dx];
        if (L >= 0){
          float4 tv = __ldg(T + ((dy*3+dx)*JJ + L)*32 + lane);
          a0+=tv.x; a1+=tv.y; a2+=tv.z; a3+=tv.w;
        }
      }
    }
    __nv_bfloat162 p0 = __floats2bfloat162_rn(fmaxf(a0,0.f), fmaxf(a1,0.f));
    __nv_bfloat162 p1 = __floats2bfloat162_rn(fmaxf(a2,0.f), fmaxf(a3,0.f));
    uint2 pk;
    pk.x = *reinterpret_cast<uint32_t*>(&p0);
    pk.y = *reinterpret_cast<uint32_t*>(&p1);
    *(uint2*)(g_actvh + ((size_t)((b*HH+h)*WW + w))*NHH + lane*4) = pk;
  }
}

__global__ void k_stats(const float* __restrict__ x, const float* __restrict__ nv){
  int bc = blockIdx.x; int b = bc >> 8; int c = bc & 255;
  const float4* xp = (const float4*)(x + (size_t)bc*HW);
  const float4* np = (const float4*)(g_noiseT + (size_t)b*HW);
  float nvc = nv[c];
  float s=0.f, s2=0.f;
  for(int i=threadIdx.x;i<HW/4;i+=256){
    float4 xv = xp[i], nn = np[i];
    float v0 = fmaf(nn.x, nvc, xv.x);
    float v1 = fmaf(nn.y, nvc, xv.y);
    float v2 = fmaf(nn.z, nvc, xv.z);
    float v3 = fmaf(nn.w, nvc, xv.w);
    s += v0+v1+v2+v3;
    s2 = fmaf(v0,v0,s2); s2 = fmaf(v1,v1,s2);
    s2 = fmaf(v2,v2,s2); s2 = fmaf(v3,v3,s2);
  }
  __shared__ float rs[8], rs2[8];
  #pragma unroll
  for(int o=16;o;o>>=1){ s += __shfl_xor_sync(0xffffffffu,s,o); s2 += __shfl_xor_sync(0xffffffffu,s2,o); }
  if((threadIdx.x & 31)==0){ rs[threadIdx.x>>5]=s; rs2[threadIdx.x>>5]=s2; }
  __syncthreads();
  if(threadIdx.x < 32){
    s  = (threadIdx.x<8)? rs[threadIdx.x]  : 0.f;
    s2 = (threadIdx.x<8)? rs2[threadIdx.x] : 0.f;
    #pragma unroll
    for(int o=4;o;o>>=1){ s += __shfl_xor_sync(0xffffffffu,s,o); s2 += __shfl_xor_sync(0xffffffffu,s2,o); }
    if(threadIdx.x==0){
      float m = s * (1.f/HW);
      float var = s2 * (1.f/HW) - m*m;
      g_mean[bc]=m; g_rstd[bc]=rsqrtf(var + 1e-5f);
    }
  }
}

// =================== warp-MMA implicit-GEMM conv3x3 (bf16 HMMA, cp.async) ===================
#define OFF_A0 0
#define OFF_A1 16384
#define OFF_B0 32768
#define OFF_B1 49152
#define OFF_BIAS 67584
#define SMEM_DYN 68096

__device__ __forceinline__ void stage_cp(int c, uint32_t sbase, uint32_t a_off, uint32_t b_off,
                                         int b, int h, int n0, int tid){
  int tap = c >> 1, half = c & 1;
  int dy = tap/3 - 1, dx = tap%3 - 1;
  const float4* srcB = (const float4*)g_Wh + ((size_t)c*512 + n0)*8;
  #pragma unroll
  for (int i = 0; i < 4; i++){
    int idx = tid + i*256;
    int n = idx >> 3, blk = idx & 7;
    uint32_t off = (uint32_t)(n*128 + blk*16);
    off ^= (off>>3)&0x70;
    CP_ASYNC16(sbase + b_off + off, srcB + idx);
  }
  int hh = h + dy;
  #pragma unroll
  for (int i = 0; i < 4; i++){
    int idx = tid + i*256;
    int p = idx >> 3, blk = idx & 7;
    int w = p + dx;
    int ok = ((unsigned)hh < HH) && ((unsigned)w < WW);
    const float4* src = (const float4*)g_actvh +
        ((size_t)((b*HH + (ok?hh:0))*WW + (ok?w:0)))*16 + half*8 + blk;
    uint32_t off = (uint32_t)(p*128 + blk*16);
    off ^= (off>>3)&0x70;
    CP_ASYNC16_Z(sbase + a_off + off, src, ok ? 16 : 0);
  }
  CP_COMMIT();
}

__global__ void __launch_bounds__(256,2) k_mma_conv(const float* __restrict__ sgb,
                                                    const float* __restrict__ sbb,
                                                    const float* __restrict__ bgp,
                                                    const float* __restrict__ bbp){
  extern __shared__ __align__(1024) char sm[];
  uint32_t sbase = smem_u32(sm);
  int tid = threadIdx.x, lane = tid & 31, wid = tid >> 5;
  int n0 = blockIdx.x * 128;
  int h = blockIdx.y, b = blockIdx.z;
  int wm = wid & 3, wn = wid >> 2;

  if (tid < 128){
    int n = n0 + tid;
    float ga = 1.f/(1.f+expf(-bgp[0]));
    float ba = 1.f/(1.f+expf(-bbp[0]));
    float v = (n < 256) ? (1.f-ga)*sgb[n] : (1.f-ba)*sbb[n-256];
    ((float*)(sm + OFF_BIAS))[tid] = v;
  }

  float acc[2][8][4];
  #pragma unroll
  for (int mt=0;mt<2;mt++)
    #pragma unroll
    for (int nt=0;nt<8;nt++)
      #pragma unroll
      for (int q=0;q<4;q++) acc[mt][nt][q]=0.f;

  stage_cp(0, sbase, OFF_A0, OFF_B0, b, h, n0, tid);

  #pragma unroll 1
  for (int c = 0; c < 18; c++){
    CP_WAIT0();
    __syncthreads();
    int buf = c & 1;
    if (c + 1 < 18)
      stage_cp(c+1, sbase, buf ? OFF_A0 : OFF_A1, buf ? OFF_B0 : OFF_B1, b, h, n0, tid);
    uint32_t aB = sbase + (buf ? OFF_A1 : OFF_A0);
    uint32_t bB = sbase + (buf ? OFF_B1 : OFF_B0);
    #pragma unroll
    for (int ks = 0; ks < 4; ks++){
      uint32_t a0[4], a1[4];
      {
        uint32_t row = wm*32 + (lane & 15);
        uint32_t off = row*128 + ks*32 + (lane>>4)*16;
        off ^= (off>>3)&0x70;
        LDSM_X4(a0[0],a0[1],a0[2],a0[3], aB + off);
        row += 16;
        off = row*128 + ks*32 + (lane>>4)*16;
        off ^= (off>>3)&0x70;
        LDSM_X4(a1[0],a1[1],a1[2],a1[3], aB + off);
      }
      uint32_t bf[8][2];
      #pragma unroll
      for (int j = 0; j < 4; j++){
        uint32_t row = wn*64 + j*16 + ((lane>>4)<<3) + (lane & 7);
        uint32_t off = row*128 + ks*32 + ((lane>>3)&1)*16;
        off ^= (off>>3)&0x70;
        uint32_t r0,r1,r2,r3;
        LDSM_X4(r0,r1,r2,r3, bB + off);
        bf[2*j][0]=r0; bf[2*j][1]=r1; bf[2*j+1][0]=r2; bf[2*j+1][1]=r3;
      }
      #pragma unroll
      for (int nt = 0; nt < 8; nt++){
        MMA16816(acc[0][nt], a0, bf[nt]);
        MMA16816(acc[1][nt], a1, bf[nt]);
      }
    }
  }
  __syncthreads();

  // epilogue: restage fp32 to smem [nl][132], then coalesced fp16 stores
  float* sEp = (float*)sm;
  #pragma unroll
  for (int mt=0;mt<2;mt++)
    #pragma unroll
    for (int nt=0;nt<8;nt++){
      int p0 = wm*32 + mt*16 + (lane>>2);
      int nl = wn*64 + nt*8 + (lane&3)*2;
      sEp[nl*132 + p0]       = acc[mt][nt][0];
      sEp[(nl+1)*132 + p0]   = acc[mt][nt][1];
      sEp[nl*132 + p0+8]     = acc[mt][nt][2];
      sEp[(nl+1)*132 + p0+8] = acc[mt][nt][3];
    }
  __syncthreads();
  const float* bias = (const float*)(sm + OFF_BIAS);
  __half* outb = g_spoutH + ((size_t)b*NN2 + n0)*HW + h*WW;
  #pragma unroll 2
  for (int i = tid; i < 128*16; i += 256){
    int nl = i >> 4, q = i & 15;
    float4 v0 = *(float4*)&sEp[nl*132 + q*8];
    float4 v1 = *(float4*)&sEp[nl*132 + q*8 + 4];
    float bv = bias[nl];
    __half2 h0 = __floats2half2_rn(v0.x+bv, v0.y+bv);
    __half2 h1 = __floats2half2_rn(v0.z+bv, v0.w+bv);
    __half2 h2 = __floats2half2_rn(v1.x+bv, v1.y+bv);
    __half2 h3 = __floats2half2_rn(v1.z+bv, v1.w+bv);
    uint4 pk;
    pk.x = h2_bits(h0);
    pk.y = h2_bits(h1);
    pk.z = h2_bits(h2);
    pk.w = h2_bits(h3);
    *(uint4*)&outb[(size_t)nl*HW + q*8] = pk;
  }
}

// ---------------- final: fp16 table-gather + spade blend + instance norm (R10 version) ----------------
extern __shared__ float sdyn[];
__global__ void __launch_bounds__(256) k_final(const float* __restrict__ x, const int* __restrict__ seg,
    const float* __restrict__ nv, const float* __restrict__ cgb, const float* __restrict__ cbb,
    float* __restrict__ out){
  int bx = blockIdx.x;
  int w0 = (bx & 3) * 32;
  int h = (bx >> 2) & 127;
  int b = bx >> 9;
  __shared__ int sL[3*34];
  float* sg = sdyn;
  float* sb = sdyn + 32*257;
  int tid = threadIdx.x;
  for(int i=tid;i<3*34;i+=256){
    int dy=i/34, ccc=i%34;
    int hh=h+dy-1, ww2=w0+ccc-1;
    sL[i] = ((unsigned)hh<HH && (unsigned)ww2<WW) ? seg[(b*HH+hh)*WW+ww2] : -1;
  }
  __syncthreads();
  {
    int cp = tid & 127, half = tid >> 7;
    int c0 = cp*2;
    float bg0 = g_ga*cgb[c0], bg1 = g_ga*cgb[c0+1];
    float bb0 = g_ba*cbb[c0], bb1 = g_ba*cbb[c0+1];
    const char* G = (const char*)g_GtabH;
    for(int p = half*16; p < half*16+16; p++){
      float agm0=bg0, abt0=bb0, agm1=bg1, abt1=bb1;
      #pragma unroll
      for(int dy=0;dy<3;dy++){
        #pragma unroll
        for(int dx=0;dx<3;dx++){
          int L = sL[dy*34 + p + dx];
          if(L >= 0){
            float2 raw = __ldg((const float2*)(G + (((size_t)((b*JJ+L)*9 + dy*3+dx))*CC + c0)*4));
            __half2 v0 = *reinterpret_cast<__half2*>(&raw.x);
            __half2 v1 = *reinterpret_cast<__half2*>(&raw.y);
            float2 f0 = __half22float2(v0), f1 = __half22float2(v1);
            agm0 += f0.x; abt0 += f0.y;
            agm1 += f1.x; abt1 += f1.y;
          }
        }
      }
      sg[p*257+c0]=agm0; sg[p*257+c0+1]=agm1;
      sb[p*257+c0]=abt0; sb[p*257+c0+1]=abt1;
    }
  }
  __syncthreads();
  int lane = tid & 31, cw = tid >> 5;
  int ww = w0 + lane;
  float nval = g_noiseT[(b*HH+h)*WW+ww];
  const __half* spg = g_spoutH + (size_t)b*NN2*HW + h*WW + ww;
  for(int c = cw; c < CC; c += 8){
    int bc = b*CC + c;
    float m = g_mean[bc], rs = g_rstd[bc];
    float xv = x[(size_t)bc*HW + h*WW + ww];
    float v = (fmaf(nval, nv[c], xv) - m)*rs;
    float gm = sg[lane*257+c] + __half2float(spg[(size_t)c*HW]);
    float bt = sb[lane*257+c] + __half2float(spg[(size_t)(c+256)*HW]);
    out[(size_t)bc*HW + h*WW + ww] = fmaf(v, gm, v + bt);
  }
}

// ---------------- launch ----------------
extern "C" void kernel_launch(void* const* d_in, const int* in_sizes, int n_in,
                              void* d_out, int out_size) {
  const float* x     = (const float*)d_in[0];
  const int*   seg   = (const int*)  d_in[1];
  const float* style = (const float*)d_in[2];
  const float* noise = (const float*)d_in[3];
  const float* nv    = (const float*)d_in[4];
  const float* bg    = (const float*)d_in[5];
  const float* bb    = (const float*)d_in[6];
  const float* fcw   = (const float*)d_in[7];
  const float* fcb   = (const float*)d_in[8];
  const float* cgw   = (const float*)d_in[9];
  const float* cgb   = (const float*)d_in[10];
  const float* cbw   = (const float*)d_in[11];
  const float* cbb   = (const float*)d_in[12];
  const float* spw   = (const float*)d_in[13];
  const float* spb   = (const float*)d_in[14];
  const float* sgw   = (const float*)d_in[15];
  const float* sgb   = (const float*)d_in[16];
  const float* sbw   = (const float*)d_in[17];
  const float* sbb   = (const float*)d_in[18];
  float* out = (float*)d_out;

  cudaFuncSetAttribute(k_final, cudaFuncAttributeMaxDynamicSharedMemorySize, 2*32*257*4);
  cudaFuncSetAttribute(k_mma_conv, cudaFuncAttributeMaxDynamicSharedMemorySize, SMEM_DYN);

  bool ov = (g_s2 != nullptr);
  cudaStream_t sb = ov ? g_s2 : (cudaStream_t)0;
  if (ov){
    if (cudaEventRecord(g_evF, 0) != cudaSuccess ||
        cudaStreamWaitEvent(sb, g_evF, 0) != cudaSuccess){
      ov = false; sb = (cudaStream_t)0;
    }
  }

  // chain A (capture stream): spwt -> actv -> wh -> conv (conv = 4th launch for ncu)
  k_spwt  <<<(9*JJ*NHH+255)/256,256,0,0>>>(spw);
  k_actv  <<<BB*HH,256,0,0>>>(seg,spb);
  k_wh    <<<(18*512*64)/256,256,0,0>>>(sgw,sbw,bg,bb);
  k_mma_conv<<<dim3(4,HH,BB),256,SMEM_DYN,0>>>(sgb,sbb,bg,bb);

  // chain B (side stream, overlaps the conv): gates, noise, mu, Wt, Gtab, stats
  k_init  <<<1,1,0,sb>>>(bg,bb);
  k_noiseT<<<dim3(4,4,8),dim3(32,32),0,sb>>>(noise);
  k_mu    <<<BJ,256,0,sb>>>(style,fcw,fcb);
  k_wt    <<<(2*9*SS*CC)/256,256,0,sb>>>(cgw,cbw);
  k_gtab  <<<dim3(18,19),256,0,sb>>>();
  k_stats <<<BB*CC,256,0,sb>>>(x,nv);

  if (ov){
    cudaEventRecord(g_evJ, sb);
    cudaStreamWaitEvent(0, g_evJ, 0);
  }
  k_final <<<BB*HH*4,256,2*32*257*4,0>>>(x,seg,nv,cgb,cbb,out);
}

// round 15
// speedup vs baseline: 1.3116x; 1.0180x over previous
#include <cuda_runtime.h>
#include <cuda_bf16.h>
#include <cuda_fp16.h>
#include <cstdint>
#include <math.h>

#define BB 8
#define CC 256
#define HH 128
#define WW 128
#define JJ 19
#define SS 512
#define NHH 128
#define NN2 512
#define HW (HH*WW)
#define BJ (BB*JJ)

// ======================= helpers =======================
__device__ __forceinline__ uint32_t smem_u32(const void* p){
  uint32_t a;
  asm("{ .reg .u64 t; cvta.to.shared.u64 t, %1; cvt.u32.u64 %0, t; }" : "=r"(a) : "l"(p));
  return a;
}
__device__ __forceinline__ uint32_t h2_bits(__half2 h){
  return *reinterpret_cast<uint32_t*>(&h);
}
#define LDSM_X4(r0,r1,r2,r3, a) \
  asm volatile("ldmatrix.sync.aligned.m8n8.x4.shared.b16 {%0,%1,%2,%3}, [%4];" \
    : "=r"(r0),"=r"(r1),"=r"(r2),"=r"(r3) : "r"(a))
#define MMA16816(d, a, b) \
  asm volatile("mma.sync.aligned.m16n8k16.row.col.f32.bf16.bf16.f32 " \
    "{%0,%1,%2,%3}, {%4,%5,%6,%7}, {%8,%9}, {%0,%1,%2,%3};" \
    : "+f"((d)[0]),"+f"((d)[1]),"+f"((d)[2]),"+f"((d)[3]) \
    : "r"((a)[0]),"r"((a)[1]),"r"((a)[2]),"r"((a)[3]), "r"((b)[0]),"r"((b)[1]))
#define CP_ASYNC16(dst, src) \
  asm volatile("cp.async.cg.shared.global [%0], [%1], 16;" :: "r"(dst), "l"(src) : "memory")
#define CP_ASYNC16_Z(dst, src, sz) \
  asm volatile("cp.async.cg.shared.global [%0], [%1], 16, %2;" :: "r"(dst), "l"(src), "r"(sz) : "memory")
#define CP_COMMIT() asm volatile("cp.async.commit_group;" ::: "memory")
#define CP_WAIT0()  asm volatile("cp.async.wait_group 0;" ::: "memory")

// ---------------- device scratch ----------------
__device__ float g_ga, g_ba;
__device__ float g_mu[BJ*SS];
__device__ float g_Wt[2*9*SS*CC];
__device__ __align__(16) __half g_GtabH[(size_t)BJ*9*CC*2]; // [bj][tap][c]{gamma,beta} fp16
__device__ __align__(16) float g_SPWt[9*JJ*NHH];            // [tap][j][nh]
__device__ __nv_bfloat16 g_Wh[18*512*64];                   // [chunk=tap*2+half][n][64]
__device__ __nv_bfloat16 g_actvh[(size_t)BB*HW*NHH];        // [b][h][w][nh]
__device__ float g_noiseT[BB*HW];
__device__ __half g_spoutH[(size_t)BB*NN2*HW];              // [b][n][h][w] fp16
__device__ float g_mean[BB*CC], g_rstd[BB*CC];

// ---------------- streams/events for graph fork-join (created pre-capture) ----------------
static cudaStream_t g_s2 = nullptr;
static cudaEvent_t g_evF = nullptr, g_evB = nullptr, g_evC0 = nullptr, g_evF0 = nullptr;
namespace {
struct StreamInit {
  StreamInit(){
    if (cudaStreamCreateWithFlags(&g_s2, cudaStreamNonBlocking) != cudaSuccess){ g_s2 = nullptr; return; }
    if (cudaEventCreateWithFlags(&g_evF, cudaEventDisableTiming) != cudaSuccess ||
        cudaEventCreateWithFlags(&g_evB, cudaEventDisableTiming) != cudaSuccess ||
        cudaEventCreateWithFlags(&g_evC0, cudaEventDisableTiming) != cudaSuccess ||
        cudaEventCreateWithFlags(&g_evF0, cudaEventDisableTiming) != cudaSuccess){
      g_s2 = nullptr;
    }
  }
};
static StreamInit g_stream_init;
}

// ---------------- tiny init ----------------
__global__ void k_init(const float* __restrict__ bg, const float* __restrict__ bb){
  g_ga = 1.f/(1.f+expf(-bg[0]));
  g_ba = 1.f/(1.f+expf(-bb[0]));
}

__global__ void k_noiseT(const float* __restrict__ noise){
  __shared__ float t[32][33];
  int b = blockIdx.z;
  int h0 = blockIdx.x*32, w0 = blockIdx.y*32;
  int w = w0 + threadIdx.y, h = h0 + threadIdx.x;
  t[threadIdx.y][threadIdx.x] = noise[(b*WW + w)*HH + h];
  __syncthreads();
  h = h0 + threadIdx.y; w = w0 + threadIdx.x;
  g_noiseT[(b*HH + h)*WW + w] = t[threadIdx.x][threadIdx.y];
}

__global__ void k_mu(const float* __restrict__ style, const float* __restrict__ fcw,
                     const float* __restrict__ fcb){
  int b = blockIdx.x / JJ, j = blockIdx.x % JJ;
  __shared__ __align__(16) float sv[SS];
  for (int i=threadIdx.x;i<SS;i+=256) sv[i]=style[((size_t)b*JJ+j)*SS+i];
  __syncthreads();
  const float4* s4 = (const float4*)sv;
  #pragma unroll
  for (int oo=0;oo<2;oo++){
    int o = threadIdx.x + oo*256;
    const float4* w4 = (const float4*)(fcw + ((size_t)j*SS + o)*SS);
    float a = 0.f;
    for(int i=0;i<SS/4;i++){
      float4 wv=w4[i], svv=s4[i];
      a = fmaf(wv.x,svv.x,a); a = fmaf(wv.y,svv.y,a);
      a = fmaf(wv.z,svv.z,a); a = fmaf(wv.w,svv.w,a);
    }
    g_mu[((size_t)b*JJ+j)*SS+o]=fmaxf(a + fcb[j*SS+o],0.f);
  }
}

__global__ void k_wt(const float* __restrict__ gw, const float* __restrict__ bw){
  int idx = blockIdx.x*256+threadIdx.x;
  int c = idx % CC; int s = (idx/CC)%SS; int tap = (idx/(CC*SS))%9; int t = idx/(CC*SS*9);
  const float* w = t? bw : gw;
  float sc = t? g_ba : g_ga;
  g_Wt[idx] = sc * w[((size_t)c*SS+s)*9+tap];
}

__global__ void k_gtab(){
  int ttap = blockIdx.x;           // t*9+tap
  int mc = blockIdx.y;
  int c = threadIdx.x;
  __shared__ float smu[8][128];
  float acc[8];
  #pragma unroll
  for(int m=0;m<8;m++)acc[m]=0.f;
  for(int kc=0;kc<4;kc++){
    for(int i=threadIdx.x;i<8*128;i+=256){
      int m=i>>7,k=i&127;
      smu[m][k]=g_mu[(size_t)(mc*8+m)*SS + kc*128 + k];
    }
    __syncthreads();
    const float* wp = g_Wt + ((size_t)ttap*SS + kc*128)*CC + c;
    #pragma unroll 4
    for(int k=0;k<128;k++){
      float wv = wp[(size_t)k*CC];
      #pragma unroll
      for(int m=0;m<8;m++) acc[m]=fmaf(wv,smu[m][k],acc[m]);
    }
    __syncthreads();
  }
  int t=ttap/9, tap=ttap%9;
  #pragma unroll
  for(int m=0;m<8;m++){
    int bj=mc*8+m;
    g_GtabH[(((size_t)bj*9 + tap)*CC + c)*2 + t] = __float2half(acc[m]);
  }
}

__global__ void k_spwt(const float* __restrict__ spw){
  int idx = blockIdx.x*256+threadIdx.x;
  if(idx < 9*JJ*NHH){
    int nh = idx % NHH; int j = (idx/NHH)%JJ; int tap = idx/(NHH*JJ);
    g_SPWt[idx] = spw[(nh*JJ + j)*9 + tap];
  }
}

// pack blend-scaled spade conv weights to bf16 chunk layout [tap*2+half][n][64]
__global__ void k_wh(const float* __restrict__ sgw, const float* __restrict__ sbw,
                     const float* __restrict__ bgp, const float* __restrict__ bbp){
  int idx = blockIdx.x*256 + threadIdx.x;   // 18*512*64
  float ga = 1.f/(1.f+expf(-bgp[0]));
  float ba = 1.f/(1.f+expf(-bbp[0]));
  int l = idx & 63;
  int n = (idx >> 6) & 511;
  int chunk = idx >> 15;
  int tap = chunk >> 1, half = chunk & 1;
  int kc = half*64 + l;
  float v;
  if (n < 256) v = (1.f-ga)*sgw[((size_t)n*NHH + kc)*9 + tap];
  else         v = (1.f-ba)*sbw[((size_t)(n-256)*NHH + kc)*9 + tap];
  g_Wh[idx] = __float2bfloat16(v);
}

// actv = relu(table-sum over label neighborhood + bias), vectorized 4-wide over nh
__global__ void k_actv(const int* __restrict__ seg, const float* __restrict__ spb){
  int b = blockIdx.x >> 7, h = blockIdx.x & 127;
  __shared__ int sL[3][130];
  __shared__ float sB[128];
  int tid = threadIdx.x;
  for(int i=tid;i<3*130;i+=256){
    int dy=i/130, cc=i%130;
    int hh=h+dy-1, ww=cc-1;
    sL[dy][cc] = ((unsigned)hh<HH && (unsigned)ww<WW)? seg[(b*HH+hh)*WW+ww] : -1;
  }
  if (tid < 128) sB[tid] = spb[tid];
  __syncthreads();
  int lane = tid & 31, warp = tid >> 5;
  const float4* T = (const float4*)g_SPWt;
  float b0 = sB[lane*4], b1 = sB[lane*4+1], b2 = sB[lane*4+2], b3 = sB[lane*4+3];
  #pragma unroll 1
  for (int w = warp; w < WW; w += 8){
    float a0=b0, a1=b1, a2=b2, a3=b3;
    #pragma unroll
    for (int dy=0;dy<3;dy++){
      #pragma unroll
      for (int dx=0;dx<3;dx++){
        int L = sL[dy][w+dx];
        if (L >= 0){
          float4 tv = __ldg(T + ((dy*3+dx)*JJ + L)*32 + lane);
          a0+=tv.x; a1+=tv.y; a2+=tv.z; a3+=tv.w;
        }
      }
    }
    __nv_bfloat162 p0 = __floats2bfloat162_rn(fmaxf(a0,0.f), fmaxf(a1,0.f));
    __nv_bfloat162 p1 = __floats2bfloat162_rn(fmaxf(a2,0.f), fmaxf(a3,0.f));
    uint2 pk;
    pk.x = *reinterpret_cast<uint32_t*>(&p0);
    pk.y = *reinterpret_cast<uint32_t*>(&p1);
    *(uint2*)(g_actvh + ((size_t)((b*HH+h)*WW + w))*NHH + lane*4) = pk;
  }
}

__global__ void k_stats(const float* __restrict__ x, const float* __restrict__ nv){
  int bc = blockIdx.x; int b = bc >> 8; int c = bc & 255;
  const float4* xp = (const float4*)(x + (size_t)bc*HW);
  const float4* np = (const float4*)(g_noiseT + (size_t)b*HW);
  float nvc = nv[c];
  float s=0.f, s2=0.f;
  for(int i=threadIdx.x;i<HW/4;i+=256){
    float4 xv = xp[i], nn = np[i];
    float v0 = fmaf(nn.x, nvc, xv.x);
    float v1 = fmaf(nn.y, nvc, xv.y);
    float v2 = fmaf(nn.z, nvc, xv.z);
    float v3 = fmaf(nn.w, nvc, xv.w);
    s += v0+v1+v2+v3;
    s2 = fmaf(v0,v0,s2); s2 = fmaf(v1,v1,s2);
    s2 = fmaf(v2,v2,s2); s2 = fmaf(v3,v3,s2);
  }
  __shared__ float rs[8], rs2[8];
  #pragma unroll
  for(int o=16;o;o>>=1){ s += __shfl_xor_sync(0xffffffffu,s,o); s2 += __shfl_xor_sync(0xffffffffu,s2,o); }
  if((threadIdx.x & 31)==0){ rs[threadIdx.x>>5]=s; rs2[threadIdx.x>>5]=s2; }
  __syncthreads();
  if(threadIdx.x < 32){
    s  = (threadIdx.x<8)? rs[threadIdx.x]  : 0.f;
    s2 = (threadIdx.x<8)? rs2[threadIdx.x] : 0.f;
    #pragma unroll
    for(int o=4;o;o>>=1){ s += __shfl_xor_sync(0xffffffffu,s,o); s2 += __shfl_xor_sync(0xffffffffu,s2,o); }
    if(threadIdx.x==0){
      float m = s * (1.f/HW);
      float var = s2 * (1.f/HW) - m*m;
      g_mean[bc]=m; g_rstd[bc]=rsqrtf(var + 1e-5f);
    }
  }
}

// =================== warp-MMA implicit-GEMM conv3x3 (bf16 HMMA, cp.async) ===================
#define OFF_A0 0
#define OFF_A1 16384
#define OFF_B0 32768
#define OFF_B1 49152
#define OFF_BIAS 67584
#define SMEM_DYN 68096

__device__ __forceinline__ void stage_cp(int c, uint32_t sbase, uint32_t a_off, uint32_t b_off,
                                         int b, int h, int n0, int tid){
  int tap = c >> 1, half = c & 1;
  int dy = tap/3 - 1, dx = tap%3 - 1;
  const float4* srcB = (const float4*)g_Wh + ((size_t)c*512 + n0)*8;
  #pragma unroll
  for (int i = 0; i < 4; i++){
    int idx = tid + i*256;
    int n = idx >> 3, blk = idx & 7;
    uint32_t off = (uint32_t)(n*128 + blk*16);
    off ^= (off>>3)&0x70;
    CP_ASYNC16(sbase + b_off + off, srcB + idx);
  }
  int hh = h + dy;
  #pragma unroll
  for (int i = 0; i < 4; i++){
    int idx = tid + i*256;
    int p = idx >> 3, blk = idx & 7;
    int w = p + dx;
    int ok = ((unsigned)hh < HH) && ((unsigned)w < WW);
    const float4* src = (const float4*)g_actvh +
        ((size_t)((b*HH + (ok?hh:0))*WW + (ok?w:0)))*16 + half*8 + blk;
    uint32_t off = (uint32_t)(p*128 + blk*16);
    off ^= (off>>3)&0x70;
    CP_ASYNC16_Z(sbase + a_off + off, src, ok ? 16 : 0);
  }
  CP_COMMIT();
}

__global__ void __launch_bounds__(256,2) k_mma_conv(const float* __restrict__ sgb,
                                                    const float* __restrict__ sbb,
                                                    const float* __restrict__ bgp,
                                                    const float* __restrict__ bbp,
                                                    int bbase){
  extern __shared__ __align__(1024) char sm[];
  uint32_t sbase = smem_u32(sm);
  int tid = threadIdx.x, lane = tid & 31, wid = tid >> 5;
  int n0 = blockIdx.x * 128;
  int h = blockIdx.y, b = blockIdx.z + bbase;
  int wm = wid & 3, wn = wid >> 2;

  if (tid < 128){
    int n = n0 + tid;
    float ga = 1.f/(1.f+expf(-bgp[0]));
    float ba = 1.f/(1.f+expf(-bbp[0]));
    float v = (n < 256) ? (1.f-ga)*sgb[n] : (1.f-ba)*sbb[n-256];
    ((float*)(sm + OFF_BIAS))[tid] = v;
  }

  float acc[2][8][4];
  #pragma unroll
  for (int mt=0;mt<2;mt++)
    #pragma unroll
    for (int nt=0;nt<8;nt++)
      #pragma unroll
      for (int q=0;q<4;q++) acc[mt][nt][q]=0.f;

  stage_cp(0, sbase, OFF_A0, OFF_B0, b, h, n0, tid);

  #pragma unroll 1
  for (int c = 0; c < 18; c++){
    CP_WAIT0();
    __syncthreads();
    int buf = c & 1;
    if (c + 1 < 18)
      stage_cp(c+1, sbase, buf ? OFF_A0 : OFF_A1, buf ? OFF_B0 : OFF_B1, b, h, n0, tid);
    uint32_t aB = sbase + (buf ? OFF_A1 : OFF_A0);
    uint32_t bB = sbase + (buf ? OFF_B1 : OFF_B0);
    #pragma unroll
    for (int ks = 0; ks < 4; ks++){
      uint32_t a0[4], a1[4];
      {
        uint32_t row = wm*32 + (lane & 15);
        uint32_t off = row*128 + ks*32 + (lane>>4)*16;
        off ^= (off>>3)&0x70;
        LDSM_X4(a0[0],a0[1],a0[2],a0[3], aB + off);
        row += 16;
        off = row*128 + ks*32 + (lane>>4)*16;
        off ^= (off>>3)&0x70;
        LDSM_X4(a1[0],a1[1],a1[2],a1[3], aB + off);
      }
      uint32_t bf[8][2];
      #pragma unroll
      for (int j = 0; j < 4; j++){
        uint32_t row = wn*64 + j*16 + ((lane>>4)<<3) + (lane & 7);
        uint32_t off = row*128 + ks*32 + ((lane>>3)&1)*16;
        off ^= (off>>3)&0x70;
        uint32_t r0,r1,r2,r3;
        LDSM_X4(r0,r1,r2,r3, bB + off);
        bf[2*j][0]=r0; bf[2*j][1]=r1; bf[2*j+1][0]=r2; bf[2*j+1][1]=r3;
      }
      #pragma unroll
      for (int nt = 0; nt < 8; nt++){
        MMA16816(acc[0][nt], a0, bf[nt]);
        MMA16816(acc[1][nt], a1, bf[nt]);
      }
    }
  }
  __syncthreads();

  // epilogue: restage fp32 to smem [nl][132], then coalesced fp16 stores
  float* sEp = (float*)sm;
  #pragma unroll
  for (int mt=0;mt<2;mt++)
    #pragma unroll
    for (int nt=0;nt<8;nt++){
      int p0 = wm*32 + mt*16 + (lane>>2);
      int nl = wn*64 + nt*8 + (lane&3)*2;
      sEp[nl*132 + p0]       = acc[mt][nt][0];
      sEp[(nl+1)*132 + p0]   = acc[mt][nt][1];
      sEp[nl*132 + p0+8]     = acc[mt][nt][2];
      sEp[(nl+1)*132 + p0+8] = acc[mt][nt][3];
    }
  __syncthreads();
  const float* bias = (const float*)(sm + OFF_BIAS);
  __half* outb = g_spoutH + ((size_t)b*NN2 + n0)*HW + h*WW;
  #pragma unroll 2
  for (int i = tid; i < 128*16; i += 256){
    int nl = i >> 4, q = i & 15;
    float4 v0 = *(float4*)&sEp[nl*132 + q*8];
    float4 v1 = *(float4*)&sEp[nl*132 + q*8 + 4];
    float bv = bias[nl];
    __half2 h0 = __floats2half2_rn(v0.x+bv, v0.y+bv);
    __half2 h1 = __floats2half2_rn(v0.z+bv, v0.w+bv);
    __half2 h2 = __floats2half2_rn(v1.x+bv, v1.y+bv);
    __half2 h3 = __floats2half2_rn(v1.z+bv, v1.w+bv);
    uint4 pk;
    pk.x = h2_bits(h0);
    pk.y = h2_bits(h1);
    pk.z = h2_bits(h2);
    pk.w = h2_bits(h3);
    *(uint4*)&outb[(size_t)nl*HW + q*8] = pk;
  }
}

// ---------------- final: fp16 table-gather + spade blend + instance norm ----------------
extern __shared__ float sdyn[];
__global__ void __launch_bounds__(256) k_final(const float* __restrict__ x, const int* __restrict__ seg,
    const float* __restrict__ nv, const float* __restrict__ cgb, const float* __restrict__ cbb,
    float* __restrict__ out, int bbase){
  int bx = blockIdx.x;
  int w0 = (bx & 3) * 32;
  int h = (bx >> 2) & 127;
  int b = (bx >> 9) + bbase;
  __shared__ int sL[3*34];
  float* sg = sdyn;
  float* sb = sdyn + 32*257;
  int tid = threadIdx.x;
  for(int i=tid;i<3*34;i+=256){
    int dy=i/34, ccc=i%34;
    int hh=h+dy-1, ww2=w0+ccc-1;
    sL[i] = ((unsigned)hh<HH && (unsigned)ww2<WW) ? seg[(b*HH+hh)*WW+ww2] : -1;
  }
  __syncthreads();
  {
    int cp = tid & 127, half = tid >> 7;
    int c0 = cp*2;
    float bg0 = g_ga*cgb[c0], bg1 = g_ga*cgb[c0+1];
    float bb0 = g_ba*cbb[c0], bb1 = g_ba*cbb[c0+1];
    const char* G = (const char*)g_GtabH;
    for(int p = half*16; p < half*16+16; p++){
      float agm0=bg0, abt0=bb0, agm1=bg1, abt1=bb1;
      #pragma unroll
      for(int dy=0;dy<3;dy++){
        #pragma unroll
        for(int dx=0;dx<3;dx++){
          int L = sL[dy*34 + p + dx];
          if(L >= 0){
            float2 raw = __ldg((const float2*)(G + (((size_t)((b*JJ+L)*9 + dy*3+dx))*CC + c0)*4));
            __half2 v0 = *reinterpret_cast<__half2*>(&raw.x);
            __half2 v1 = *reinterpret_cast<__half2*>(&raw.y);
            float2 f0 = __half22float2(v0), f1 = __half22float2(v1);
            agm0 += f0.x; abt0 += f0.y;
            agm1 += f1.x; abt1 += f1.y;
          }
        }
      }
      sg[p*257+c0]=agm0; sg[p*257+c0+1]=agm1;
      sb[p*257+c0]=abt0; sb[p*257+c0+1]=abt1;
    }
  }
  __syncthreads();
  int lane = tid & 31, cw = tid >> 5;
  int ww = w0 + lane;
  float nval = g_noiseT[(b*HH+h)*WW+ww];
  const __half* spg = g_spoutH + (size_t)b*NN2*HW + h*WW + ww;
  for(int c = cw; c < CC; c += 8){
    int bc = b*CC + c;
    float m = g_mean[bc], rs = g_rstd[bc];
    float xv = x[(size_t)bc*HW + h*WW + ww];
    float v = (fmaf(nval, nv[c], xv) - m)*rs;
    float gm = sg[lane*257+c] + __half2float(spg[(size_t)c*HW]);
    float bt = sb[lane*257+c] + __half2float(spg[(size_t)(c+256)*HW]);
    out[(size_t)bc*HW + h*WW + ww] = fmaf(v, gm, v + bt);
  }
}

// ---------------- launch ----------------
extern "C" void kernel_launch(void* const* d_in, const int* in_sizes, int n_in,
                              void* d_out, int out_size) {
  const float* x     = (const float*)d_in[0];
  const int*   seg   = (const int*)  d_in[1];
  const float* style = (const float*)d_in[2];
  const float* noise = (const float*)d_in[3];
  const float* nv    = (const float*)d_in[4];
  const float* bg    = (const float*)d_in[5];
  const float* bb    = (const float*)d_in[6];
  const float* fcw   = (const float*)d_in[7];
  const float* fcb   = (const float*)d_in[8];
  const float* cgw   = (const float*)d_in[9];
  const float* cgb   = (const float*)d_in[10];
  const float* cbw   = (const float*)d_in[11];
  const float* cbb   = (const float*)d_in[12];
  const float* spw   = (const float*)d_in[13];
  const float* spb   = (const float*)d_in[14];
  const float* sgw   = (const float*)d_in[15];
  const float* sgb   = (const float*)d_in[16];
  const float* sbw   = (const float*)d_in[17];
  const float* sbb   = (const float*)d_in[18];
  float* out = (float*)d_out;

  cudaFuncSetAttribute(k_final, cudaFuncAttributeMaxDynamicSharedMemorySize, 2*32*257*4);
  cudaFuncSetAttribute(k_mma_conv, cudaFuncAttributeMaxDynamicSharedMemorySize, SMEM_DYN);

  bool ov = (g_s2 != nullptr);
  cudaStream_t sb = ov ? g_s2 : (cudaStream_t)0;
  if (ov){
    if (cudaEventRecord(g_evF, 0) != cudaSuccess ||
        cudaStreamWaitEvent(sb, g_evF, 0) != cudaSuccess){
      ov = false; sb = (cudaStream_t)0;
    }
  }

  // chain A (capture stream): prefix -> conv half0 (4th launch for ncu) -> conv half1
  k_spwt  <<<(9*JJ*NHH+255)/256,256,0,0>>>(spw);
  k_actv  <<<BB*HH,256,0,0>>>(seg,spb);
  k_wh    <<<(18*512*64)/256,256,0,0>>>(sgw,sbw,bg,bb);
  k_mma_conv<<<dim3(4,HH,BB/2),256,SMEM_DYN,0>>>(sgb,sbb,bg,bb,0);
  if (ov) cudaEventRecord(g_evC0, 0);
  k_mma_conv<<<dim3(4,HH,BB/2),256,SMEM_DYN,0>>>(sgb,sbb,bg,bb,BB/2);

  // chain B (side stream): gates, noise, mu, Wt, Gtab, stats — overlaps the conv
  k_init  <<<1,1,0,sb>>>(bg,bb);
  k_noiseT<<<dim3(4,4,8),dim3(32,32),0,sb>>>(noise);
  k_mu    <<<BJ,256,0,sb>>>(style,fcw,fcb);
  k_wt    <<<(2*9*SS*CC)/256,256,0,sb>>>(cgw,cbw);
  k_gtab  <<<dim3(18,19),256,0,sb>>>();
  k_stats <<<BB*CC,256,0,sb>>>(x,nv);

  if (ov){
    cudaEventRecord(g_evB, sb);
    // final half0 on side stream: after chain B (program order) + conv half0 (event)
    cudaStreamWaitEvent(sb, g_evC0, 0);
    k_final <<<(BB/2)*HH*4,256,2*32*257*4,sb>>>(x,seg,nv,cgb,cbb,out,0);
    cudaEventRecord(g_evF0, sb);
    // final half1 on capture stream: after conv half1 (program order) + chain B (event)
    cudaStreamWaitEvent(0, g_evB, 0);
    k_final <<<(BB/2)*HH*4,256,2*32*257*4,0>>>(x,seg,nv,cgb,cbb,out,BB/2);
    cudaStreamWaitEvent(0, g_evF0, 0);
  } else {
    k_final <<<(BB/2)*HH*4,256,2*32*257*4,0>>>(x,seg,nv,cgb,cbb,out,0);
    k_final <<<(BB/2)*HH*4,256,2*32*257*4,0>>>(x,seg,nv,cgb,cbb,out,BB/2);
  }
}

// round 16
// speedup vs baseline: 1.3255x; 1.0106x over previous
#include <cuda_runtime.h>
#include <cuda_bf16.h>
#include <cuda_fp16.h>
#include <cstdint>
#include <math.h>

#define BB 8
#define CC 256
#define HH 128
#define WW 128
#define JJ 19
#define SS 512
#define NHH 128
#define NN2 512
#define HW (HH*WW)
#define BJ (BB*JJ)

// ======================= helpers =======================
__device__ __forceinline__ uint32_t smem_u32(const void* p){
  uint32_t a;
  asm("{ .reg .u64 t; cvta.to.shared.u64 t, %1; cvt.u32.u64 %0, t; }" : "=r"(a) : "l"(p));
  return a;
}
__device__ __forceinline__ uint32_t h2_bits(__half2 h){
  return *reinterpret_cast<uint32_t*>(&h);
}
#define LDSM_X4(r0,r1,r2,r3, a) \
  asm volatile("ldmatrix.sync.aligned.m8n8.x4.shared.b16 {%0,%1,%2,%3}, [%4];" \
    : "=r"(r0),"=r"(r1),"=r"(r2),"=r"(r3) : "r"(a))
#define MMA16816(d, a, b) \
  asm volatile("mma.sync.aligned.m16n8k16.row.col.f32.bf16.bf16.f32 " \
    "{%0,%1,%2,%3}, {%4,%5,%6,%7}, {%8,%9}, {%0,%1,%2,%3};" \
    : "+f"((d)[0]),"+f"((d)[1]),"+f"((d)[2]),"+f"((d)[3]) \
    : "r"((a)[0]),"r"((a)[1]),"r"((a)[2]),"r"((a)[3]), "r"((b)[0]),"r"((b)[1]))
#define CP_ASYNC16(dst, src) \
  asm volatile("cp.async.cg.shared.global [%0], [%1], 16;" :: "r"(dst), "l"(src) : "memory")
#define CP_ASYNC16_Z(dst, src, sz) \
  asm volatile("cp.async.cg.shared.global [%0], [%1], 16, %2;" :: "r"(dst), "l"(src), "r"(sz) : "memory")
#define CP_COMMIT() asm volatile("cp.async.commit_group;" ::: "memory")
#define CP_WAIT0()  asm volatile("cp.async.wait_group 0;" ::: "memory")

// ---------------- device scratch ----------------
__device__ float g_ga, g_ba;
__device__ float g_mu[BJ*SS];
__device__ float g_Wt[2*9*SS*CC];
__device__ __align__(16) __half g_GtabH[(size_t)BJ*9*CC*2]; // [bj][tap][c]{gamma,beta} fp16
__device__ __align__(16) float g_SPWt[9*JJ*NHH];            // [tap][j][nh]
__device__ __nv_bfloat16 g_Wh[18*512*64];                   // [chunk=tap*2+half][n][64]
__device__ __nv_bfloat16 g_actvh[(size_t)BB*HW*NHH];        // [b][h][w][nh]
__device__ float g_noiseT[BB*HW];
__device__ __half g_spoutH[(size_t)BB*NN2*HW];              // [b][n][h][w] fp16
__device__ float g_mean[BB*CC], g_rstd[BB*CC];

// ---------------- streams/events for graph fork-join (created pre-capture) ----------------
static cudaStream_t g_s2 = nullptr, g_s3 = nullptr;
static cudaEvent_t g_evF = nullptr, g_evW = nullptr, g_evB = nullptr;
static cudaEvent_t g_evC0 = nullptr, g_evC1 = nullptr, g_evC2 = nullptr, g_evF2 = nullptr;
namespace {
struct StreamInit {
  StreamInit(){
    bool ok = cudaStreamCreateWithFlags(&g_s2, cudaStreamNonBlocking) == cudaSuccess &&
              cudaStreamCreateWithFlags(&g_s3, cudaStreamNonBlocking) == cudaSuccess &&
              cudaEventCreateWithFlags(&g_evF, cudaEventDisableTiming) == cudaSuccess &&
              cudaEventCreateWithFlags(&g_evW, cudaEventDisableTiming) == cudaSuccess &&
              cudaEventCreateWithFlags(&g_evB, cudaEventDisableTiming) == cudaSuccess &&
              cudaEventCreateWithFlags(&g_evC0, cudaEventDisableTiming) == cudaSuccess &&
              cudaEventCreateWithFlags(&g_evC1, cudaEventDisableTiming) == cudaSuccess &&
              cudaEventCreateWithFlags(&g_evC2, cudaEventDisableTiming) == cudaSuccess &&
              cudaEventCreateWithFlags(&g_evF2, cudaEventDisableTiming) == cudaSuccess;
    if (!ok) g_s2 = nullptr;
  }
};
static StreamInit g_stream_init;
}

// ---------------- tiny init ----------------
__global__ void k_init(const float* __restrict__ bg, const float* __restrict__ bb){
  g_ga = 1.f/(1.f+expf(-bg[0]));
  g_ba = 1.f/(1.f+expf(-bb[0]));
}

__global__ void k_noiseT(const float* __restrict__ noise){
  __shared__ float t[32][33];
  int b = blockIdx.z;
  int h0 = blockIdx.x*32, w0 = blockIdx.y*32;
  int w = w0 + threadIdx.y, h = h0 + threadIdx.x;
  t[threadIdx.y][threadIdx.x] = noise[(b*WW + w)*HH + h];
  __syncthreads();
  h = h0 + threadIdx.y; w = w0 + threadIdx.x;
  g_noiseT[(b*HH + h)*WW + w] = t[threadIdx.x][threadIdx.y];
}

__global__ void k_mu(const float* __restrict__ style, const float* __restrict__ fcw,
                     const float* __restrict__ fcb){
  int b = blockIdx.x / JJ, j = blockIdx.x % JJ;
  __shared__ __align__(16) float sv[SS];
  for (int i=threadIdx.x;i<SS;i+=256) sv[i]=style[((size_t)b*JJ+j)*SS+i];
  __syncthreads();
  const float4* s4 = (const float4*)sv;
  #pragma unroll
  for (int oo=0;oo<2;oo++){
    int o = threadIdx.x + oo*256;
    const float4* w4 = (const float4*)(fcw + ((size_t)j*SS + o)*SS);
    float a = 0.f;
    for(int i=0;i<SS/4;i++){
      float4 wv=w4[i], svv=s4[i];
      a = fmaf(wv.x,svv.x,a); a = fmaf(wv.y,svv.y,a);
      a = fmaf(wv.z,svv.z,a); a = fmaf(wv.w,svv.w,a);
    }
    g_mu[((size_t)b*JJ+j)*SS+o]=fmaxf(a + fcb[j*SS+o],0.f);
  }
}

__global__ void k_wt(const float* __restrict__ gw, const float* __restrict__ bw){
  int idx = blockIdx.x*256+threadIdx.x;
  int c = idx % CC; int s = (idx/CC)%SS; int tap = (idx/(CC*SS))%9; int t = idx/(CC*SS*9);
  const float* w = t? bw : gw;
  float sc = t? g_ba : g_ga;
  g_Wt[idx] = sc * w[((size_t)c*SS+s)*9+tap];
}

__global__ void k_gtab(){
  int ttap = blockIdx.x;           // t*9+tap
  int mc = blockIdx.y;
  int c = threadIdx.x;
  __shared__ float smu[8][128];
  float acc[8];
  #pragma unroll
  for(int m=0;m<8;m++)acc[m]=0.f;
  for(int kc=0;kc<4;kc++){
    for(int i=threadIdx.x;i<8*128;i+=256){
      int m=i>>7,k=i&127;
      smu[m][k]=g_mu[(size_t)(mc*8+m)*SS + kc*128 + k];
    }
    __syncthreads();
    const float* wp = g_Wt + ((size_t)ttap*SS + kc*128)*CC + c;
    #pragma unroll 4
    for(int k=0;k<128;k++){
      float wv = wp[(size_t)k*CC];
      #pragma unroll
      for(int m=0;m<8;m++) acc[m]=fmaf(wv,smu[m][k],acc[m]);
    }
    __syncthreads();
  }
  int t=ttap/9, tap=ttap%9;
  #pragma unroll
  for(int m=0;m<8;m++){
    int bj=mc*8+m;
    g_GtabH[(((size_t)bj*9 + tap)*CC + c)*2 + t] = __float2half(acc[m]);
  }
}

__global__ void k_spwt(const float* __restrict__ spw){
  int idx = blockIdx.x*256+threadIdx.x;
  if(idx < 9*JJ*NHH){
    int nh = idx % NHH; int j = (idx/NHH)%JJ; int tap = idx/(NHH*JJ);
    g_SPWt[idx] = spw[(nh*JJ + j)*9 + tap];
  }
}

// pack blend-scaled spade conv weights to bf16 chunk layout [tap*2+half][n][64]
__global__ void k_wh(const float* __restrict__ sgw, const float* __restrict__ sbw,
                     const float* __restrict__ bgp, const float* __restrict__ bbp){
  int idx = blockIdx.x*256 + threadIdx.x;   // 18*512*64
  float ga = 1.f/(1.f+expf(-bgp[0]));
  float ba = 1.f/(1.f+expf(-bbp[0]));
  int l = idx & 63;
  int n = (idx >> 6) & 511;
  int chunk = idx >> 15;
  int tap = chunk >> 1, half = chunk & 1;
  int kc = half*64 + l;
  float v;
  if (n < 256) v = (1.f-ga)*sgw[((size_t)n*NHH + kc)*9 + tap];
  else         v = (1.f-ba)*sbw[((size_t)(n-256)*NHH + kc)*9 + tap];
  g_Wh[idx] = __float2bfloat16(v);
}

// actv = relu(table-sum over label neighborhood + bias), vectorized 4-wide over nh
__global__ void k_actv(const int* __restrict__ seg, const float* __restrict__ spb){
  int b = blockIdx.x >> 7, h = blockIdx.x & 127;
  __shared__ int sL[3][130];
  __shared__ float sB[128];
  int tid = threadIdx.x;
  for(int i=tid;i<3*130;i+=256){
    int dy=i/130, cc=i%130;
    int hh=h+dy-1, ww=cc-1;
    sL[dy][cc] = ((unsigned)hh<HH && (unsigned)ww<WW)? seg[(b*HH+hh)*WW+ww] : -1;
  }
  if (tid < 128) sB[tid] = spb[tid];
  __syncthreads();
  int lane = tid & 31, warp = tid >> 5;
  const float4* T = (const float4*)g_SPWt;
  float b0 = sB[lane*4], b1 = sB[lane*4+1], b2 = sB[lane*4+2], b3 = sB[lane*4+3];
  #pragma unroll 1
  for (int w = warp; w < WW; w += 8){
    float a0=b0, a1=b1, a2=b2, a3=b3;
    #pragma unroll
    for (int dy=0;dy<3;dy++){
      #pragma unroll
      for (int dx=0;dx<3;dx++){
        int L = sL[dy][w+dx];
        if (L >= 0){
          float4 tv = __ldg(T + ((dy*3+dx)*JJ + L)*32 + lane);
          a0+=tv.x; a1+=tv.y; a2+=tv.z; a3+=tv.w;
        }
      }
    }
    __nv_bfloat162 p0 = __floats2bfloat162_rn(fmaxf(a0,0.f), fmaxf(a1,0.f));
    __nv_bfloat162 p1 = __floats2bfloat162_rn(fmaxf(a2,0.f), fmaxf(a3,0.f));
    uint2 pk;
    pk.x = *reinterpret_cast<uint32_t*>(&p0);
    pk.y = *reinterpret_cast<uint32_t*>(&p1);
    *(uint2*)(g_actvh + ((size_t)((b*HH+h)*WW + w))*NHH + lane*4) = pk;
  }
}

__global__ void k_stats(const float* __restrict__ x, const float* __restrict__ nv){
  int bc = blockIdx.x; int b = bc >> 8; int c = bc & 255;
  const float4* xp = (const float4*)(x + (size_t)bc*HW);
  const float4* np = (const float4*)(g_noiseT + (size_t)b*HW);
  float nvc = nv[c];
  float s=0.f, s2=0.f;
  for(int i=threadIdx.x;i<HW/4;i+=256){
    float4 xv = xp[i], nn = np[i];
    float v0 = fmaf(nn.x, nvc, xv.x);
    float v1 = fmaf(nn.y, nvc, xv.y);
    float v2 = fmaf(nn.z, nvc, xv.z);
    float v3 = fmaf(nn.w, nvc, xv.w);
    s += v0+v1+v2+v3;
    s2 = fmaf(v0,v0,s2); s2 = fmaf(v1,v1,s2);
    s2 = fmaf(v2,v2,s2); s2 = fmaf(v3,v3,s2);
  }
  __shared__ float rs[8], rs2[8];
  #pragma unroll
  for(int o=16;o;o>>=1){ s += __shfl_xor_sync(0xffffffffu,s,o); s2 += __shfl_xor_sync(0xffffffffu,s2,o); }
  if((threadIdx.x & 31)==0){ rs[threadIdx.x>>5]=s; rs2[threadIdx.x>>5]=s2; }
  __syncthreads();
  if(threadIdx.x < 32){
    s  = (threadIdx.x<8)? rs[threadIdx.x]  : 0.f;
    s2 = (threadIdx.x<8)? rs2[threadIdx.x] : 0.f;
    #pragma unroll
    for(int o=4;o;o>>=1){ s += __shfl_xor_sync(0xffffffffu,s,o); s2 += __shfl_xor_sync(0xffffffffu,s2,o); }
    if(threadIdx.x==0){
      float m = s * (1.f/HW);
      float var = s2 * (1.f/HW) - m*m;
      g_mean[bc]=m; g_rstd[bc]=rsqrtf(var + 1e-5f);
    }
  }
}

// =================== warp-MMA implicit-GEMM conv3x3 (bf16 HMMA, cp.async) ===================
#define OFF_A0 0
#define OFF_A1 16384
#define OFF_B0 32768
#define OFF_B1 49152
#define OFF_BIAS 67584
#define SMEM_DYN 68096

__device__ __forceinline__ void stage_cp(int c, uint32_t sbase, uint32_t a_off, uint32_t b_off,
                                         int b, int h, int n0, int tid){
  int tap = c >> 1, half = c & 1;
  int dy = tap/3 - 1, dx = tap%3 - 1;
  const float4* srcB = (const float4*)g_Wh + ((size_t)c*512 + n0)*8;
  #pragma unroll
  for (int i = 0; i < 4; i++){
    int idx = tid + i*256;
    int n = idx >> 3, blk = idx & 7;
    uint32_t off = (uint32_t)(n*128 + blk*16);
    off ^= (off>>3)&0x70;
    CP_ASYNC16(sbase + b_off + off, srcB + idx);
  }
  int hh = h + dy;
  #pragma unroll
  for (int i = 0; i < 4; i++){
    int idx = tid + i*256;
    int p = idx >> 3, blk = idx & 7;
    int w = p + dx;
    int ok = ((unsigned)hh < HH) && ((unsigned)w < WW);
    const float4* src = (const float4*)g_actvh +
        ((size_t)((b*HH + (ok?hh:0))*WW + (ok?w:0)))*16 + half*8 + blk;
    uint32_t off = (uint32_t)(p*128 + blk*16);
    off ^= (off>>3)&0x70;
    CP_ASYNC16_Z(sbase + a_off + off, src, ok ? 16 : 0);
  }
  CP_COMMIT();
}

__global__ void __launch_bounds__(256,2) k_mma_conv(const float* __restrict__ sgb,
                                                    const float* __restrict__ sbb,
                                                    const float* __restrict__ bgp,
                                                    const float* __restrict__ bbp,
                                                    int bbase){
  extern __shared__ __align__(1024) char sm[];
  uint32_t sbase = smem_u32(sm);
  int tid = threadIdx.x, lane = tid & 31, wid = tid >> 5;
  int n0 = blockIdx.x * 128;
  int h = blockIdx.y, b = blockIdx.z + bbase;
  int wm = wid & 3, wn = wid >> 2;

  if (tid < 128){
    int n = n0 + tid;
    float ga = 1.f/(1.f+expf(-bgp[0]));
    float ba = 1.f/(1.f+expf(-bbp[0]));
    float v = (n < 256) ? (1.f-ga)*sgb[n] : (1.f-ba)*sbb[n-256];
    ((float*)(sm + OFF_BIAS))[tid] = v;
  }

  float acc[2][8][4];
  #pragma unroll
  for (int mt=0;mt<2;mt++)
    #pragma unroll
    for (int nt=0;nt<8;nt++)
      #pragma unroll
      for (int q=0;q<4;q++) acc[mt][nt][q]=0.f;

  stage_cp(0, sbase, OFF_A0, OFF_B0, b, h, n0, tid);

  #pragma unroll 1
  for (int c = 0; c < 18; c++){
    CP_WAIT0();
    __syncthreads();
    int buf = c & 1;
    if (c + 1 < 18)
      stage_cp(c+1, sbase, buf ? OFF_A0 : OFF_A1, buf ? OFF_B0 : OFF_B1, b, h, n0, tid);
    uint32_t aB = sbase + (buf ? OFF_A1 : OFF_A0);
    uint32_t bB = sbase + (buf ? OFF_B1 : OFF_B0);
    #pragma unroll
    for (int ks = 0; ks < 4; ks++){
      uint32_t a0[4], a1[4];
      {
        uint32_t row = wm*32 + (lane & 15);
        uint32_t off = row*128 + ks*32 + (lane>>4)*16;
        off ^= (off>>3)&0x70;
        LDSM_X4(a0[0],a0[1],a0[2],a0[3], aB + off);
        row += 16;
        off = row*128 + ks*32 + (lane>>4)*16;
        off ^= (off>>3)&0x70;
        LDSM_X4(a1[0],a1[1],a1[2],a1[3], aB + off);
      }
      uint32_t bf[8][2];
      #pragma unroll
      for (int j = 0; j < 4; j++){
        uint32_t row = wn*64 + j*16 + ((lane>>4)<<3) + (lane & 7);
        uint32_t off = row*128 + ks*32 + ((lane>>3)&1)*16;
        off ^= (off>>3)&0x70;
        uint32_t r0,r1,r2,r3;
        LDSM_X4(r0,r1,r2,r3, bB + off);
        bf[2*j][0]=r0; bf[2*j][1]=r1; bf[2*j+1][0]=r2; bf[2*j+1][1]=r3;
      }
      #pragma unroll
      for (int nt = 0; nt < 8; nt++){
        MMA16816(acc[0][nt], a0, bf[nt]);
        MMA16816(acc[1][nt], a1, bf[nt]);
      }
    }
  }
  __syncthreads();

  // epilogue: restage fp32 to smem [nl][132], then coalesced fp16 stores
  float* sEp = (float*)sm;
  #pragma unroll
  for (int mt=0;mt<2;mt++)
    #pragma unroll
    for (int nt=0;nt<8;nt++){
      int p0 = wm*32 + mt*16 + (lane>>2);
      int nl = wn*64 + nt*8 + (lane&3)*2;
      sEp[nl*132 + p0]       = acc[mt][nt][0];
      sEp[(nl+1)*132 + p0]   = acc[mt][nt][1];
      sEp[nl*132 + p0+8]     = acc[mt][nt][2];
      sEp[(nl+1)*132 + p0+8] = acc[mt][nt][3];
    }
  __syncthreads();
  const float* bias = (const float*)(sm + OFF_BIAS);
  __half* outb = g_spoutH + ((size_t)b*NN2 + n0)*HW + h*WW;
  #pragma unroll 2
  for (int i = tid; i < 128*16; i += 256){
    int nl = i >> 4, q = i & 15;
    float4 v0 = *(float4*)&sEp[nl*132 + q*8];
    float4 v1 = *(float4*)&sEp[nl*132 + q*8 + 4];
    float bv = bias[nl];
    __half2 h0 = __floats2half2_rn(v0.x+bv, v0.y+bv);
    __half2 h1 = __floats2half2_rn(v0.z+bv, v0.w+bv);
    __half2 h2 = __floats2half2_rn(v1.x+bv, v1.y+bv);
    __half2 h3 = __floats2half2_rn(v1.z+bv, v1.w+bv);
    uint4 pk;
    pk.x = h2_bits(h0);
    pk.y = h2_bits(h1);
    pk.z = h2_bits(h2);
    pk.w = h2_bits(h3);
    *(uint4*)&outb[(size_t)nl*HW + q*8] = pk;
  }
}

// ---------------- final: fp16 table-gather + spade blend + instance norm ----------------
extern __shared__ float sdyn[];
__global__ void __launch_bounds__(256) k_final(const float* __restrict__ x, const int* __restrict__ seg,
    const float* __restrict__ nv, const float* __restrict__ cgb, const float* __restrict__ cbb,
    float* __restrict__ out, int bbase){
  int bx = blockIdx.x;
  int w0 = (bx & 3) * 32;
  int h = (bx >> 2) & 127;
  int b = (bx >> 9) + bbase;
  __shared__ int sL[3*34];
  float* sg = sdyn;
  float* sb = sdyn + 32*257;
  int tid = threadIdx.x;
  for(int i=tid;i<3*34;i+=256){
    int dy=i/34, ccc=i%34;
    int hh=h+dy-1, ww2=w0+ccc-1;
    sL[i] = ((unsigned)hh<HH && (unsigned)ww2<WW) ? seg[(b*HH+hh)*WW+ww2] : -1;
  }
  __syncthreads();
  {
    int cp = tid & 127, half = tid >> 7;
    int c0 = cp*2;
    float bg0 = g_ga*cgb[c0], bg1 = g_ga*cgb[c0+1];
    float bb0 = g_ba*cbb[c0], bb1 = g_ba*cbb[c0+1];
    const char* G = (const char*)g_GtabH;
    for(int p = half*16; p < half*16+16; p++){
      float agm0=bg0, abt0=bb0, agm1=bg1, abt1=bb1;
      #pragma unroll
      for(int dy=0;dy<3;dy++){
        #pragma unroll
        for(int dx=0;dx<3;dx++){
          int L = sL[dy*34 + p + dx];
          if(L >= 0){
            float2 raw = __ldg((const float2*)(G + (((size_t)((b*JJ+L)*9 + dy*3+dx))*CC + c0)*4));
            __half2 v0 = *reinterpret_cast<__half2*>(&raw.x);
            __half2 v1 = *reinterpret_cast<__half2*>(&raw.y);
            float2 f0 = __half22float2(v0), f1 = __half22float2(v1);
            agm0 += f0.x; abt0 += f0.y;
            agm1 += f1.x; abt1 += f1.y;
          }
        }
      }
      sg[p*257+c0]=agm0; sg[p*257+c0+1]=agm1;
      sb[p*257+c0]=abt0; sb[p*257+c0+1]=abt1;
    }
  }
  __syncthreads();
  int lane = tid & 31, cw = tid >> 5;
  int ww = w0 + lane;
  float nval = g_noiseT[(b*HH+h)*WW+ww];
  const __half* spg = g_spoutH + (size_t)b*NN2*HW + h*WW + ww;
  for(int c = cw; c < CC; c += 8){
    int bc = b*CC + c;
    float m = g_mean[bc], rs = g_rstd[bc];
    float xv = x[(size_t)bc*HW + h*WW + ww];
    float v = (fmaf(nval, nv[c], xv) - m)*rs;
    float gm = sg[lane*257+c] + __half2float(spg[(size_t)c*HW]);
    float bt = sb[lane*257+c] + __half2float(spg[(size_t)(c+256)*HW]);
    out[(size_t)bc*HW + h*WW + ww] = fmaf(v, gm, v + bt);
  }
}

// ---------------- launch ----------------
extern "C" void kernel_launch(void* const* d_in, const int* in_sizes, int n_in,
                              void* d_out, int out_size) {
  const float* x     = (const float*)d_in[0];
  const int*   seg   = (const int*)  d_in[1];
  const float* style = (const float*)d_in[2];
  const float* noise = (const float*)d_in[3];
  const float* nv    = (const float*)d_in[4];
  const float* bg    = (const float*)d_in[5];
  const float* bb    = (const float*)d_in[6];
  const float* fcw   = (const float*)d_in[7];
  const float* fcb   = (const float*)d_in[8];
  const float* cgw   = (const float*)d_in[9];
  const float* cgb   = (const float*)d_in[10];
  const float* cbw   = (const float*)d_in[11];
  const float* cbb   = (const float*)d_in[12];
  const float* spw   = (const float*)d_in[13];
  const float* spb   = (const float*)d_in[14];
  const float* sgw   = (const float*)d_in[15];
  const float* sgb   = (const float*)d_in[16];
  const float* sbw   = (const float*)d_in[17];
  const float* sbb   = (const float*)d_in[18];
  float* out = (float*)d_out;

  cudaFuncSetAttribute(k_final, cudaFuncAttributeMaxDynamicSharedMemorySize, 2*32*257*4);
  cudaFuncSetAttribute(k_mma_conv, cudaFuncAttributeMaxDynamicSharedMemorySize, SMEM_DYN);

  bool ov = (g_s2 != nullptr);
  if (ov){
    if (cudaEventRecord(g_evF, 0) != cudaSuccess ||
        cudaStreamWaitEvent(g_s2, g_evF, 0) != cudaSuccess ||
        cudaStreamWaitEvent(g_s3, g_evF, 0) != cudaSuccess){
      ov = false;
    }
  }

  if (ov){
    const int FB = 2;                    // batches of 2 images
    // s0: spwt -> actv ; s3: wh (parallel). Launch order keeps conv0 as 4th launch.
    k_spwt  <<<(9*JJ*NHH+255)/256,256,0,0>>>(spw);
    k_actv  <<<BB*HH,256,0,0>>>(seg,spb);
    k_wh    <<<(18*512*64)/256,256,0,g_s3>>>(sgw,sbw,bg,bb);
    cudaEventRecord(g_evW, g_s3);
    cudaStreamWaitEvent(0, g_evW, 0);
    k_mma_conv<<<dim3(4,HH,FB),256,SMEM_DYN,0>>>(sgb,sbb,bg,bb,0);
    cudaEventRecord(g_evC0, 0);
    k_mma_conv<<<dim3(4,HH,FB),256,SMEM_DYN,0>>>(sgb,sbb,bg,bb,2);
    cudaEventRecord(g_evC1, 0);
    k_mma_conv<<<dim3(4,HH,FB),256,SMEM_DYN,0>>>(sgb,sbb,bg,bb,4);
    cudaEventRecord(g_evC2, 0);
    k_mma_conv<<<dim3(4,HH,FB),256,SMEM_DYN,0>>>(sgb,sbb,bg,bb,6);

    // chain B on s2 (overlaps conv)
    k_init  <<<1,1,0,g_s2>>>(bg,bb);
    k_noiseT<<<dim3(4,4,8),dim3(32,32),0,g_s2>>>(noise);
    k_mu    <<<BJ,256,0,g_s2>>>(style,fcw,fcb);
    k_wt    <<<(2*9*SS*CC)/256,256,0,g_s2>>>(cgw,cbw);
    k_gtab  <<<dim3(18,19),256,0,g_s2>>>();
    k_stats <<<BB*CC,256,0,g_s2>>>(x,nv);
    cudaEventRecord(g_evB, g_s2);

    // finals 0..2 chase on s2 (after chain B by program order + conv_i events)
    cudaStreamWaitEvent(g_s2, g_evC0, 0);
    k_final <<<FB*HH*4,256,2*32*257*4,g_s2>>>(x,seg,nv,cgb,cbb,out,0);
    cudaStreamWaitEvent(g_s2, g_evC1, 0);
    k_final <<<FB*HH*4,256,2*32*257*4,g_s2>>>(x,seg,nv,cgb,cbb,out,2);
    cudaStreamWaitEvent(g_s2, g_evC2, 0);
    k_final <<<FB*HH*4,256,2*32*257*4,g_s2>>>(x,seg,nv,cgb,cbb,out,4);
    cudaEventRecord(g_evF2, g_s2);

    // final 3 on s0 (after conv3 program order + chain B event), then join
    cudaStreamWaitEvent(0, g_evB, 0);
    k_final <<<FB*HH*4,256,2*32*257*4,0>>>(x,seg,nv,cgb,cbb,out,6);
    cudaStreamWaitEvent(0, g_evF2, 0);
  } else {
    k_spwt  <<<(9*JJ*NHH+255)/256,256>>>(spw);
    k_actv  <<<BB*HH,256>>>(seg,spb);
    k_wh    <<<(18*512*64)/256,256>>>(sgw,sbw,bg,bb);
    k_mma_conv<<<dim3(4,HH,BB),256,SMEM_DYN>>>(sgb,sbb,bg,bb,0);
    k_init  <<<1,1>>>(bg,bb);
    k_noiseT<<<dim3(4,4,8),dim3(32,32)>>>(noise);
    k_mu    <<<BJ,256>>>(style,fcw,fcb);
    k_wt    <<<(2*9*SS*CC)/256,256>>>(cgw,cbw);
    k_gtab  <<<dim3(18,19),256>>>();
    k_stats <<<BB*CC,256>>>(x,nv);
    k_final <<<BB*HH*4,256,2*32*257*4>>>(x,seg,nv,cgb,cbb,out,0);
  }
}